// round 4
// baseline (speedup 1.0000x reference)
#include <cuda_runtime.h>
#include <cuda_bf16.h>
#include <cstdint>

// Problem constants
#define BATCH 4
#define SEQ   2048
#define DIM   1024
#define NHEAD 16
#define HDIM  64
#define DFF   4096
#define NTOK  (BATCH*SEQ)          // 8192
#define MODD  6144                 // 6*DIM

// ---------------- scratch (__device__ globals; allocation-free) ----------------
__device__ float g_mod [BATCH*MODD];           // 24K floats
__device__ float g_xn  [NTOK*DIM];             // 8.4M
__device__ float g_qkv [NTOK*3*DIM];           // 25.2M
__device__ float g_q   [BATCH*NHEAD*SEQ*HDIM]; // 8.4M
__device__ float g_k   [BATCH*NHEAD*SEQ*HDIM];
__device__ float g_v   [BATCH*NHEAD*SEQ*HDIM];
__device__ float g_attn[NTOK*DIM];
__device__ float g_x1  [NTOK*DIM];
__device__ float g_h   [NTOK*DFF];             // 33.5M

// ---------------- adaLN modulation: mod = c @ ada_W + ada_b ----------------
__global__ void mod_kernel(const float* __restrict__ c,
                           const float* __restrict__ adaW,
                           const float* __restrict__ adab,
                           float* __restrict__ mod)
{
    int j = blockIdx.x * 256 + threadIdx.x;   // 0..6143
    int b = blockIdx.y;
    const float* crow = c + b * 1024;
    float acc = adab[j];
    #pragma unroll 4
    for (int k = 0; k < 1024; k++)
        acc = fmaf(__ldg(crow + k), __ldg(adaW + (size_t)k * MODD + j), acc);
    mod[b * MODD + j] = acc;
}

// ---------------- LayerNorm + adaLN modulate ----------------
__global__ void ln_mod_kernel(const float* __restrict__ x,
                              const float* __restrict__ w,
                              const float* __restrict__ mod,
                              int sh_off, int sc_off,
                              float* __restrict__ out)
{
    __shared__ float red[16];
    __shared__ float stats[2];
    int t = blockIdx.x;
    int b = t >> 11;
    const float4* xr = (const float4*)(x + (size_t)t * DIM);
    float4 xv = xr[threadIdx.x];

    float s  = xv.x + xv.y + xv.z + xv.w;
    float sq = xv.x*xv.x + xv.y*xv.y + xv.z*xv.z + xv.w*xv.w;
    #pragma unroll
    for (int o = 16; o; o >>= 1) {
        s  += __shfl_down_sync(0xffffffffu, s,  o);
        sq += __shfl_down_sync(0xffffffffu, sq, o);
    }
    int wid = threadIdx.x >> 5, lane = threadIdx.x & 31;
    if (lane == 0) { red[wid] = s; red[wid + 8] = sq; }
    __syncthreads();
    if (threadIdx.x == 0) {
        float ts = 0.f, tq = 0.f;
        #pragma unroll
        for (int i = 0; i < 8; i++) { ts += red[i]; tq += red[i + 8]; }
        float mu  = ts * (1.f / DIM);
        float var = tq * (1.f / DIM) - mu * mu;
        stats[0] = mu;
        stats[1] = rsqrtf(var + 1e-5f);
    }
    __syncthreads();
    float mu = stats[0], rstd = stats[1];

    const float* modb = mod + b * MODD;
    float4 wv = ((const float4*)w)[threadIdx.x];
    float4 sc = ((const float4*)(modb + sc_off))[threadIdx.x];
    float4 sh = ((const float4*)(modb + sh_off))[threadIdx.x];
    float4 o;
    o.x = (xv.x - mu) * rstd * wv.x * (1.f + sc.x) + sh.x;
    o.y = (xv.y - mu) * rstd * wv.y * (1.f + sc.y) + sh.y;
    o.z = (xv.z - mu) * rstd * wv.z * (1.f + sc.z) + sh.z;
    o.w = (xv.w - mu) * rstd * wv.w * (1.f + sc.w) + sh.w;
    ((float4*)(out + (size_t)t * DIM))[threadIdx.x] = o;
}

// ---------------- Generic tiled SGEMM, 128x128x16, 8x8 microtile ----------------
// MODE 0: C = A@B
// MODE 1: C = gelu_tanh(A@B + bias)
// MODE 2: C = res + g[b,col] * (A@B (+ bias))
__device__ __forceinline__ float gelu_tanh(float x)
{
    float x3 = x * x * x;
    return 0.5f * x * (1.f + tanhf(0.7978845608028654f * (x + 0.044715f * x3)));
}

template<int MODE>
__global__ __launch_bounds__(256, 2)
void gemm_kernel(const float* __restrict__ A, const float* __restrict__ Bm,
                 float* __restrict__ C, int M, int N, int K,
                 const float* __restrict__ bias,
                 const float* __restrict__ res,
                 const float* __restrict__ mod, int goff)
{
    __shared__ float As[16][132];
    __shared__ float Bs[16][128];
    int tid = threadIdx.x;
    int tr = tid >> 4, tc = tid & 15;
    int rowBase = blockIdx.y << 7;
    int colBase = blockIdx.x << 7;

    float acc[8][8] = {};
    const float* Aptr = A + (size_t)rowBase * K;

    for (int kt = 0; kt < K; kt += 16) {
        #pragma unroll
        for (int i = 0; i < 2; i++) {
            int slot = tid + (i << 8);
            int ar = slot >> 2, ak = (slot & 3) << 2;
            float4 av = *(const float4*)(Aptr + (size_t)ar * K + kt + ak);
            As[ak + 0][ar] = av.x;
            As[ak + 1][ar] = av.y;
            As[ak + 2][ar] = av.z;
            As[ak + 3][ar] = av.w;
            int br = slot >> 5, bn = (slot & 31) << 2;
            *(float4*)&Bs[br][bn] = *(const float4*)(Bm + (size_t)(kt + br) * N + colBase + bn);
        }
        __syncthreads();
        #pragma unroll
        for (int kk = 0; kk < 16; kk++) {
            float a[8], bb[8];
            *(float4*)(a)      = *(const float4*)&As[kk][tr << 3];
            *(float4*)(a + 4)  = *(const float4*)&As[kk][(tr << 3) + 4];
            *(float4*)(bb)     = *(const float4*)&Bs[kk][tc << 3];
            *(float4*)(bb + 4) = *(const float4*)&Bs[kk][(tc << 3) + 4];
            #pragma unroll
            for (int i = 0; i < 8; i++)
                #pragma unroll
                for (int j = 0; j < 8; j++)
                    acc[i][j] = fmaf(a[i], bb[j], acc[i][j]);
        }
        __syncthreads();
    }

    // epilogue
    int bidx = rowBase >> 11;   // 2048 rows per batch; blocks are 128-row aligned
    int colOff = colBase + (tc << 3);
    float gv[8], bv[8];
    if (MODE == 2) {
        const float* gm = mod + bidx * MODD + goff + colOff;
        #pragma unroll
        for (int j = 0; j < 8; j++) gv[j] = gm[j];
    }
    if (MODE >= 1) {
        #pragma unroll
        for (int j = 0; j < 8; j++) bv[j] = bias ? bias[colOff + j] : 0.f;
    }
    #pragma unroll
    for (int i = 0; i < 8; i++) {
        int r = rowBase + (tr << 3) + i;
        size_t off = (size_t)r * N + colOff;
        #pragma unroll
        for (int jj = 0; jj < 8; jj += 4) {
            float4 rv;
            if (MODE == 2) rv = *(const float4*)(res + off + jj);
            float vals[4];
            #pragma unroll
            for (int j2 = 0; j2 < 4; j2++) {
                int j = jj + j2;
                float vv = acc[i][j];
                if (MODE == 1) vv = gelu_tanh(vv + bv[j]);
                if (MODE == 2) {
                    vv += bv[j];
                    float rr = (j2 == 0) ? rv.x : (j2 == 1) ? rv.y : (j2 == 2) ? rv.z : rv.w;
                    vv = rr + gv[j] * vv;
                }
                vals[j2] = vv;
            }
            *(float4*)(C + off + jj) = make_float4(vals[0], vals[1], vals[2], vals[3]);
        }
    }
}

// ---------------- RMSNorm + RoPE for q,k; reshape v ----------------
// one warp per (b,s,h); lane handles dims lane and lane+32
__global__ void qkv_prep_kernel(const float* __restrict__ qkv,
                                const float* __restrict__ qw,
                                const float* __restrict__ kw,
                                const float* __restrict__ cosb,
                                const float* __restrict__ sinb,
                                float* __restrict__ qo,
                                float* __restrict__ ko,
                                float* __restrict__ vo)
{
    int gid  = blockIdx.x * blockDim.x + threadIdx.x;
    int lane = gid & 31;
    int widx = gid >> 5;             // 0 .. B*S*H-1
    int h = widx & 15;
    int s = (widx >> 4) & 2047;
    int b = widx >> 15;

    const float* base = qkv + (size_t)(b * SEQ + s) * (3 * DIM) + h * HDIM;
    float q1 = base[lane],            q2 = base[lane + 32];
    float k1 = base[DIM + lane],      k2 = base[DIM + lane + 32];
    float v1 = base[2 * DIM + lane],  v2 = base[2 * DIM + lane + 32];

    float ssq = q1 * q1 + q2 * q2;
    float ssk = k1 * k1 + k2 * k2;
    #pragma unroll
    for (int o = 16; o; o >>= 1) {
        ssq += __shfl_xor_sync(0xffffffffu, ssq, o);
        ssk += __shfl_xor_sync(0xffffffffu, ssk, o);
    }
    float rq = rsqrtf(ssq * (1.f / HDIM) + 1e-6f);
    float rk = rsqrtf(ssk * (1.f / HDIM) + 1e-6f);
    q1 *= rq * qw[lane];  q2 *= rq * qw[lane + 32];
    k1 *= rk * kw[lane];  k2 *= rk * kw[lane + 32];

    float c1 = cosb[s * HDIM + lane], c2 = cosb[s * HDIM + lane + 32];
    float s1 = sinb[s * HDIM + lane], s2 = sinb[s * HDIM + lane + 32];
    float oq1 = q1 * c1 - q2 * s1;
    float oq2 = q2 * c2 + q1 * s2;
    float ok1 = k1 * c1 - k2 * s1;
    float ok2 = k2 * c2 + k1 * s2;

    size_t off = ((size_t)(b * NHEAD + h) * SEQ + s) * HDIM;
    qo[off + lane] = oq1; qo[off + lane + 32] = oq2;
    ko[off + lane] = ok1; ko[off + lane + 32] = ok2;
    vo[off + lane] = v1;  vo[off + lane + 32] = v2;
}

// ---------------- Flash attention: block = 64 q rows for one (b,h) ----------------
__global__ __launch_bounds__(256)
void attn_kernel(const float* __restrict__ q, const float* __restrict__ k,
                 const float* __restrict__ v, float* __restrict__ out)
{
    __shared__ float Qt [64][64];   // [d][row]
    __shared__ float KVt[64][64];   // K: [d][col], then V: [c][d]
    __shared__ float Ss [64][64];   // scores / probs

    int tid = threadIdx.x;
    int qt = blockIdx.x, h = blockIdx.y, b = blockIdx.z;
    int bh = b * NHEAD + h;
    const float* qb = q + ((size_t)bh * SEQ + qt * 64) * HDIM;
    const float* kb = k + (size_t)bh * SEQ * HDIM;
    const float* vb = v + (size_t)bh * SEQ * HDIM;

    // load Q transposed, pre-scaled by 1/sqrt(HD)
    #pragma unroll
    for (int i = 0; i < 4; i++) {
        int slot = tid + i * 256;
        int r  = slot & 63;
        int dc = (slot >> 6) << 2;
        float4 t = *(const float4*)(qb + (size_t)r * HDIM + dc);
        Qt[dc + 0][r] = t.x * 0.125f;
        Qt[dc + 1][r] = t.y * 0.125f;
        Qt[dc + 2][r] = t.z * 0.125f;
        Qt[dc + 3][r] = t.w * 0.125f;
    }

    int tr = tid >> 4, tc = tid & 15;
    int srow = tid >> 2;            // softmax row (4 threads/row)
    int scol = (tid & 3) << 4;      // 16-col chunk
    float acc[4][4] = {};
    float m_r = -1e30f, l_r = 0.f;

    for (int kt = 0; kt < SEQ / 64; kt++) {
        __syncthreads();            // guard prior-iter PV reads of KVt/Ss
        // K tile, transposed
        #pragma unroll
        for (int i = 0; i < 4; i++) {
            int slot = tid + i * 256;
            int r  = slot & 63;
            int dc = (slot >> 6) << 2;
            float4 t = *(const float4*)(kb + (size_t)(kt * 64 + r) * HDIM + dc);
            KVt[dc + 0][r] = t.x;
            KVt[dc + 1][r] = t.y;
            KVt[dc + 2][r] = t.z;
            KVt[dc + 3][r] = t.w;
        }
        __syncthreads();

        // S = (Q^T)^T K^T : 4x4 per thread
        float sacc[4][4] = {};
        #pragma unroll 16
        for (int d = 0; d < 64; d++) {
            float4 qa = *(const float4*)&Qt[d][tr << 2];
            float4 kv = *(const float4*)&KVt[d][tc << 2];
            float a[4] = {qa.x, qa.y, qa.z, qa.w};
            float bb[4] = {kv.x, kv.y, kv.z, kv.w};
            #pragma unroll
            for (int i = 0; i < 4; i++)
                #pragma unroll
                for (int j = 0; j < 4; j++)
                    sacc[i][j] = fmaf(a[i], bb[j], sacc[i][j]);
        }
        #pragma unroll
        for (int i = 0; i < 4; i++)
            *(float4*)&Ss[(tr << 2) + i][tc << 2] =
                make_float4(sacc[i][0], sacc[i][1], sacc[i][2], sacc[i][3]);
        __syncthreads();

        // V tile ([c][d]) — overwrites KVt; concurrent with softmax on Ss
        #pragma unroll
        for (int i = 0; i < 4; i++) {
            int slot = tid + i * 256;
            int c  = slot >> 4;
            int dc = (slot & 15) << 2;
            *(float4*)&KVt[c][dc] = *(const float4*)(vb + (size_t)(kt * 64 + c) * HDIM + dc);
        }

        // online softmax: 4 threads per row, 16 cols each
        float4 sv[4];
        #pragma unroll
        for (int i = 0; i < 4; i++) sv[i] = *(float4*)&Ss[srow][scol + (i << 2)];
        float mx = sv[0].x;
        #pragma unroll
        for (int i = 0; i < 4; i++) {
            mx = fmaxf(mx, sv[i].x); mx = fmaxf(mx, sv[i].y);
            mx = fmaxf(mx, sv[i].z); mx = fmaxf(mx, sv[i].w);
        }
        mx = fmaxf(mx, __shfl_xor_sync(0xffffffffu, mx, 1));
        mx = fmaxf(mx, __shfl_xor_sync(0xffffffffu, mx, 2));
        float m_new = fmaxf(m_r, mx);
        float corr  = __expf(m_r - m_new);
        float sum = 0.f;
        #pragma unroll
        for (int i = 0; i < 4; i++) {
            sv[i].x = __expf(sv[i].x - m_new);
            sv[i].y = __expf(sv[i].y - m_new);
            sv[i].z = __expf(sv[i].z - m_new);
            sv[i].w = __expf(sv[i].w - m_new);
            sum += sv[i].x + sv[i].y + sv[i].z + sv[i].w;
        }
        sum += __shfl_xor_sync(0xffffffffu, sum, 1);
        sum += __shfl_xor_sync(0xffffffffu, sum, 2);
        l_r = l_r * corr + sum;
        m_r = m_new;
        #pragma unroll
        for (int i = 0; i < 4; i++) *(float4*)&Ss[srow][scol + (i << 2)] = sv[i];
        __syncthreads();

        // rescale + P@V
        #pragma unroll
        for (int i = 0; i < 4; i++) {
            float ci = __shfl_sync(0xffffffffu, corr, (((tr << 2) + i) & 7) << 2);
            acc[i][0] *= ci; acc[i][1] *= ci; acc[i][2] *= ci; acc[i][3] *= ci;
        }
        #pragma unroll 8
        for (int c = 0; c < 64; c++) {
            float4 vv = *(const float4*)&KVt[c][tc << 2];
            float p0 = Ss[(tr << 2) + 0][c];
            float p1 = Ss[(tr << 2) + 1][c];
            float p2 = Ss[(tr << 2) + 2][c];
            float p3 = Ss[(tr << 2) + 3][c];
            acc[0][0] = fmaf(p0, vv.x, acc[0][0]); acc[0][1] = fmaf(p0, vv.y, acc[0][1]);
            acc[0][2] = fmaf(p0, vv.z, acc[0][2]); acc[0][3] = fmaf(p0, vv.w, acc[0][3]);
            acc[1][0] = fmaf(p1, vv.x, acc[1][0]); acc[1][1] = fmaf(p1, vv.y, acc[1][1]);
            acc[1][2] = fmaf(p1, vv.z, acc[1][2]); acc[1][3] = fmaf(p1, vv.w, acc[1][3]);
            acc[2][0] = fmaf(p2, vv.x, acc[2][0]); acc[2][1] = fmaf(p2, vv.y, acc[2][1]);
            acc[2][2] = fmaf(p2, vv.z, acc[2][2]); acc[2][3] = fmaf(p2, vv.w, acc[2][3]);
            acc[3][0] = fmaf(p3, vv.x, acc[3][0]); acc[3][1] = fmaf(p3, vv.y, acc[3][1]);
            acc[3][2] = fmaf(p3, vv.z, acc[3][2]); acc[3][3] = fmaf(p3, vv.w, acc[3][3]);
        }
    }

    // epilogue: divide by l, write [B,S,H*HD]
    size_t ob = ((size_t)(b * SEQ + qt * 64)) * DIM + h * HDIM + (tc << 2);
    #pragma unroll
    for (int i = 0; i < 4; i++) {
        float li = __shfl_sync(0xffffffffu, l_r, (((tr << 2) + i) & 7) << 2);
        float inv = 1.f / li;
        *(float4*)(out + ob + (size_t)((tr << 2) + i) * DIM) =
            make_float4(acc[i][0] * inv, acc[i][1] * inv, acc[i][2] * inv, acc[i][3] * inv);
    }
}

// ---------------- launcher ----------------
extern "C" void kernel_launch(void* const* d_in, const int* in_sizes, int n_in,
                              void* d_out, int out_size)
{
    const float* x       = (const float*)d_in[0];
    const float* cosb    = (const float*)d_in[1];
    const float* sinb    = (const float*)d_in[2];
    const float* c       = (const float*)d_in[3];
    const float* norm1_w = (const float*)d_in[4];
    const float* Wqkv    = (const float*)d_in[5];
    const float* Wout    = (const float*)d_in[6];
    const float* q_norm_w= (const float*)d_in[7];
    const float* k_norm_w= (const float*)d_in[8];
    const float* norm2_w = (const float*)d_in[9];
    const float* W1      = (const float*)d_in[10];
    const float* b1      = (const float*)d_in[11];
    const float* W2      = (const float*)d_in[12];
    const float* b2      = (const float*)d_in[13];
    const float* ada_W   = (const float*)d_in[14];
    const float* ada_b   = (const float*)d_in[15];
    float* out = (float*)d_out;

    float *mod, *xn, *qkv, *qb, *kb, *vb, *attn, *x1, *hb;
    cudaGetSymbolAddress((void**)&mod,  g_mod);
    cudaGetSymbolAddress((void**)&xn,   g_xn);
    cudaGetSymbolAddress((void**)&qkv,  g_qkv);
    cudaGetSymbolAddress((void**)&qb,   g_q);
    cudaGetSymbolAddress((void**)&kb,   g_k);
    cudaGetSymbolAddress((void**)&vb,   g_v);
    cudaGetSymbolAddress((void**)&attn, g_attn);
    cudaGetSymbolAddress((void**)&x1,   g_x1);
    cudaGetSymbolAddress((void**)&hb,   g_h);

    // 1. adaLN modulation
    mod_kernel<<<dim3(MODD / 256, BATCH), 256>>>(c, ada_W, ada_b, mod);
    // 2. LN1 + modulate
    ln_mod_kernel<<<NTOK, 256>>>(x, norm1_w, mod, 0, 1024, xn);
    // 3. QKV GEMM
    gemm_kernel<0><<<dim3(3 * DIM / 128, NTOK / 128), 256>>>(
        xn, Wqkv, qkv, NTOK, 3 * DIM, DIM, nullptr, nullptr, nullptr, 0);
    // 4. RMSNorm + RoPE
    qkv_prep_kernel<<<(BATCH * SEQ * NHEAD) / 8, 256>>>(
        qkv, q_norm_w, k_norm_w, cosb, sinb, qb, kb, vb);
    // 5. attention
    attn_kernel<<<dim3(SEQ / 64, NHEAD, BATCH), 256>>>(qb, kb, vb, attn);
    // 6. out proj + gate + residual  -> x1
    gemm_kernel<2><<<dim3(DIM / 128, NTOK / 128), 256>>>(
        attn, Wout, x1, NTOK, DIM, DIM, nullptr, x, mod, 2048);
    // 7. LN2 + modulate
    ln_mod_kernel<<<NTOK, 256>>>(x1, norm2_w, mod, 3072, 4096, xn);
    // 8. MLP up + GELU
    gemm_kernel<1><<<dim3(DFF / 128, NTOK / 128), 256>>>(
        xn, W1, hb, NTOK, DFF, DIM, b1, nullptr, nullptr, 0);
    // 9. MLP down + gate + residual -> out
    gemm_kernel<2><<<dim3(DIM / 128, NTOK / 128), 256>>>(
        hb, W2, out, NTOK, DIM, DFF, b2, x1, mod, 5120);
}

// round 6
// speedup vs baseline: 1.6389x; 1.6389x over previous
#include <cuda_runtime.h>
#include <cuda_bf16.h>
#include <cstdint>

// Problem constants
#define BATCH 4
#define SEQ   2048
#define DIM   1024
#define NHEAD 16
#define HDIM  64
#define DFF   4096
#define NTOK  (BATCH*SEQ)          // 8192
#define MODD  6144                 // 6*DIM

// ---------------- scratch (__device__ globals; allocation-free) ----------------
__device__ float g_mod [BATCH*MODD];
__device__ float g_xn  [NTOK*DIM];
__device__ float g_qkv [NTOK*3*DIM];
__device__ float g_q   [BATCH*NHEAD*SEQ*HDIM];
__device__ float g_k   [BATCH*NHEAD*SEQ*HDIM];
__device__ float g_v   [BATCH*NHEAD*SEQ*HDIM];
__device__ float g_attn[NTOK*DIM];
__device__ float g_x1  [NTOK*DIM];
__device__ float g_h   [NTOK*DFF];

// ---------------- adaLN modulation: mod = c @ ada_W + ada_b ----------------
__global__ void mod_kernel(const float* __restrict__ c,
                           const float* __restrict__ adaW,
                           const float* __restrict__ adab,
                           float* __restrict__ mod)
{
    int j = blockIdx.x * 256 + threadIdx.x;
    int b = blockIdx.y;
    const float* crow = c + b * 1024;
    float acc = adab[j];
    #pragma unroll 4
    for (int k = 0; k < 1024; k++)
        acc = fmaf(__ldg(crow + k), __ldg(adaW + (size_t)k * MODD + j), acc);
    mod[b * MODD + j] = acc;
}

// ---------------- LayerNorm + adaLN modulate ----------------
__global__ void ln_mod_kernel(const float* __restrict__ x,
                              const float* __restrict__ w,
                              const float* __restrict__ mod,
                              int sh_off, int sc_off,
                              float* __restrict__ out)
{
    __shared__ float red[16];
    __shared__ float stats[2];
    int t = blockIdx.x;
    int b = t >> 11;
    const float4* xr = (const float4*)(x + (size_t)t * DIM);
    float4 xv = xr[threadIdx.x];

    float s  = xv.x + xv.y + xv.z + xv.w;
    float sq = xv.x*xv.x + xv.y*xv.y + xv.z*xv.z + xv.w*xv.w;
    #pragma unroll
    for (int o = 16; o; o >>= 1) {
        s  += __shfl_down_sync(0xffffffffu, s,  o);
        sq += __shfl_down_sync(0xffffffffu, sq, o);
    }
    int wid = threadIdx.x >> 5, lane = threadIdx.x & 31;
    if (lane == 0) { red[wid] = s; red[wid + 8] = sq; }
    __syncthreads();
    if (threadIdx.x == 0) {
        float ts = 0.f, tq = 0.f;
        #pragma unroll
        for (int i = 0; i < 8; i++) { ts += red[i]; tq += red[i + 8]; }
        float mu  = ts * (1.f / DIM);
        float var = tq * (1.f / DIM) - mu * mu;
        stats[0] = mu;
        stats[1] = rsqrtf(var + 1e-5f);
    }
    __syncthreads();
    float mu = stats[0], rstd = stats[1];

    const float* modb = mod + b * MODD;
    float4 wv = ((const float4*)w)[threadIdx.x];
    float4 sc = ((const float4*)(modb + sc_off))[threadIdx.x];
    float4 sh = ((const float4*)(modb + sh_off))[threadIdx.x];
    float4 o;
    o.x = (xv.x - mu) * rstd * wv.x * (1.f + sc.x) + sh.x;
    o.y = (xv.y - mu) * rstd * wv.y * (1.f + sc.y) + sh.y;
    o.z = (xv.z - mu) * rstd * wv.z * (1.f + sc.z) + sh.z;
    o.w = (xv.w - mu) * rstd * wv.w * (1.f + sc.w) + sh.w;
    ((float4*)(out + (size_t)t * DIM))[threadIdx.x] = o;
}

// ---------------- tf32 MMA helpers ----------------
__device__ __forceinline__ uint32_t f2tf32(float f)
{
    uint32_t u;
    asm("cvt.rna.tf32.f32 %0, %1;" : "=r"(u) : "f"(f));
    return u;
}

__device__ __forceinline__ void mma_tf32(float* c,
                                         uint32_t a0, uint32_t a1, uint32_t a2, uint32_t a3,
                                         uint32_t b0, uint32_t b1)
{
    asm volatile("mma.sync.aligned.m16n8k8.row.col.f32.tf32.tf32.f32 "
                 "{%0,%1,%2,%3}, {%4,%5,%6,%7}, {%8,%9}, {%0,%1,%2,%3};"
                 : "+f"(c[0]), "+f"(c[1]), "+f"(c[2]), "+f"(c[3])
                 : "r"(a0), "r"(a1), "r"(a2), "r"(a3), "r"(b0), "r"(b1));
}

__device__ __forceinline__ float gelu_tanh(float x)
{
    float x3 = x * x * x;
    return 0.5f * x * (1.f + tanhf(0.7978845608028654f * (x + 0.044715f * x3)));
}

// ---------------- tf32 tensor-core GEMM, 128x128 block, BK=16 ----------------
// MODE 0: C = A@B
// MODE 1: C = gelu_tanh(A@B + bias)
// MODE 2: C = res + g[b,col] * (A@B (+ bias))
#define BM 128
#define BN 128
#define BK 16
#define ASTR 20     // A smem row stride (floats): conflict-free frag loads
#define BSTR 136    // B smem row stride (floats): conflict-free frag loads

template<int MODE>
__global__ __launch_bounds__(256)
void mma_gemm(const float* __restrict__ A, const float* __restrict__ Bm,
              float* __restrict__ C, int M, int N, int K,
              const float* __restrict__ bias,
              const float* __restrict__ res,
              const float* __restrict__ mod, int goff)
{
    __shared__ uint32_t As[2][BM * ASTR];
    __shared__ uint32_t Bs[2][BK * BSTR];

    const int tid  = threadIdx.x;
    const int lane = tid & 31, warp = tid >> 5;
    const int g = lane >> 2, tg = lane & 3;
    const int warpM = warp & 1, warpN = warp >> 1;      // 2 x 4 warp grid
    const int rowBase = blockIdx.y << 7, colBase = blockIdx.x << 7;

    const int ar0 = tid >> 2, ak0 = (tid & 3) << 2;     // A loads: rows ar0, ar0+64
    const int br0 = tid >> 5, bn0 = (tid & 31) << 2;    // B loads: rows br0, br0+8

    const float* Ag = A + (size_t)rowBase * K;

    float4 stA[2], stB[2];
    #pragma unroll
    for (int i = 0; i < 2; i++) {
        stA[i] = *(const float4*)(Ag + (size_t)(ar0 + i * 64) * K + ak0);
        stB[i] = *(const float4*)(Bm + (size_t)(br0 + i * 8) * N + colBase + bn0);
    }

    auto sts = [&](int buf) {
        #pragma unroll
        for (int i = 0; i < 2; i++) {
            uint32_t* ap = &As[buf][(ar0 + i * 64) * ASTR + ak0];
            ap[0] = f2tf32(stA[i].x); ap[1] = f2tf32(stA[i].y);
            ap[2] = f2tf32(stA[i].z); ap[3] = f2tf32(stA[i].w);
            uint4 bq;
            bq.x = f2tf32(stB[i].x); bq.y = f2tf32(stB[i].y);
            bq.z = f2tf32(stB[i].z); bq.w = f2tf32(stB[i].w);
            *(uint4*)&Bs[buf][(br0 + i * 8) * BSTR + bn0] = bq;
        }
    };
    sts(0);
    __syncthreads();

    float acc[4][4][4] = {};
    const int ntiles = K >> 4;

    for (int kt = 0; kt < ntiles; kt++) {
        const int buf = kt & 1;
        if (kt + 1 < ntiles) {
            #pragma unroll
            for (int i = 0; i < 2; i++) {
                stA[i] = *(const float4*)(Ag + (size_t)(ar0 + i * 64) * K + (kt + 1) * BK + ak0);
                stB[i] = *(const float4*)(Bm + (size_t)((kt + 1) * BK + br0 + i * 8) * N + colBase + bn0);
            }
        }
        #pragma unroll
        for (int ks = 0; ks < 2; ks++) {
            const int k0 = ks << 3;
            uint32_t af[4][4], bf[4][2];
            #pragma unroll
            for (int mt = 0; mt < 4; mt++) {
                int m = (warpM << 6) + (mt << 4) + g;
                const uint32_t* asb = &As[buf][0];
                af[mt][0] = asb[(size_t)m * ASTR + k0 + tg];
                af[mt][1] = asb[(size_t)(m + 8) * ASTR + k0 + tg];
                af[mt][2] = asb[(size_t)m * ASTR + k0 + tg + 4];
                af[mt][3] = asb[(size_t)(m + 8) * ASTR + k0 + tg + 4];
            }
            #pragma unroll
            for (int nt = 0; nt < 4; nt++) {
                int n = (warpN << 5) + (nt << 3) + g;
                bf[nt][0] = Bs[buf][(k0 + tg) * BSTR + n];
                bf[nt][1] = Bs[buf][(k0 + tg + 4) * BSTR + n];
            }
            #pragma unroll
            for (int mt = 0; mt < 4; mt++)
                #pragma unroll
                for (int nt = 0; nt < 4; nt++)
                    mma_tf32(acc[mt][nt],
                             af[mt][0], af[mt][1], af[mt][2], af[mt][3],
                             bf[nt][0], bf[nt][1]);
        }
        if (kt + 1 < ntiles) sts(buf ^ 1);
        __syncthreads();
    }

    // epilogue
    const int bidx = rowBase >> 11;
    #pragma unroll
    for (int nt = 0; nt < 4; nt++) {
        int col = colBase + (warpN << 5) + (nt << 3) + (tg << 1);
        float gv0 = 0.f, gv1 = 0.f, bv0 = 0.f, bv1 = 0.f;
        if (MODE == 2) {
            const float* gm = mod + bidx * MODD + goff;
            gv0 = gm[col]; gv1 = gm[col + 1];
        }
        if (MODE >= 1 && bias) { bv0 = bias[col]; bv1 = bias[col + 1]; }
        #pragma unroll
        for (int mt = 0; mt < 4; mt++) {
            int r0 = rowBase + (warpM << 6) + (mt << 4) + g;
            #pragma unroll
            for (int half = 0; half < 2; half++) {
                int r = r0 + half * 8;
                float v0 = acc[mt][nt][half * 2];
                float v1 = acc[mt][nt][half * 2 + 1];
                size_t off = (size_t)r * N + col;
                if (MODE == 1) {
                    v0 = gelu_tanh(v0 + bv0);
                    v1 = gelu_tanh(v1 + bv1);
                } else if (MODE == 2) {
                    float2 rv = *(const float2*)(res + off);
                    v0 = rv.x + gv0 * (v0 + bv0);
                    v1 = rv.y + gv1 * (v1 + bv1);
                }
                *(float2*)(C + off) = make_float2(v0, v1);
            }
        }
    }
}

// ---------------- RMSNorm + RoPE for q,k; reshape v ----------------
__global__ void qkv_prep_kernel(const float* __restrict__ qkv,
                                const float* __restrict__ qw,
                                const float* __restrict__ kw,
                                const float* __restrict__ cosb,
                                const float* __restrict__ sinb,
                                float* __restrict__ qo,
                                float* __restrict__ ko,
                                float* __restrict__ vo)
{
    int gid  = blockIdx.x * blockDim.x + threadIdx.x;
    int lane = gid & 31;
    int widx = gid >> 5;
    int h = widx & 15;
    int s = (widx >> 4) & 2047;
    int b = widx >> 15;

    const float* base = qkv + (size_t)(b * SEQ + s) * (3 * DIM) + h * HDIM;
    float q1 = base[lane],            q2 = base[lane + 32];
    float k1 = base[DIM + lane],      k2 = base[DIM + lane + 32];
    float v1 = base[2 * DIM + lane],  v2 = base[2 * DIM + lane + 32];

    float ssq = q1 * q1 + q2 * q2;
    float ssk = k1 * k1 + k2 * k2;
    #pragma unroll
    for (int o = 16; o; o >>= 1) {
        ssq += __shfl_xor_sync(0xffffffffu, ssq, o);
        ssk += __shfl_xor_sync(0xffffffffu, ssk, o);
    }
    float rq = rsqrtf(ssq * (1.f / HDIM) + 1e-6f);
    float rk = rsqrtf(ssk * (1.f / HDIM) + 1e-6f);
    q1 *= rq * qw[lane];  q2 *= rq * qw[lane + 32];
    k1 *= rk * kw[lane];  k2 *= rk * kw[lane + 32];

    float c1 = cosb[s * HDIM + lane], c2 = cosb[s * HDIM + lane + 32];
    float s1 = sinb[s * HDIM + lane], s2 = sinb[s * HDIM + lane + 32];
    float oq1 = q1 * c1 - q2 * s1;
    float oq2 = q2 * c2 + q1 * s2;
    float ok1 = k1 * c1 - k2 * s1;
    float ok2 = k2 * c2 + k1 * s2;

    size_t off = ((size_t)(b * NHEAD + h) * SEQ + s) * HDIM;
    qo[off + lane] = oq1; qo[off + lane + 32] = oq2;
    ko[off + lane] = ok1; ko[off + lane + 32] = ok2;
    vo[off + lane] = v1;  vo[off + lane + 32] = v2;
}

// ---------------- Flash attention: block = 64 q rows for one (b,h) ----------------
__global__ __launch_bounds__(256)
void attn_kernel(const float* __restrict__ q, const float* __restrict__ k,
                 const float* __restrict__ v, float* __restrict__ out)
{
    __shared__ float Qt [64][64];
    __shared__ float KVt[64][64];
    __shared__ float Ss [64][64];

    int tid = threadIdx.x;
    int qt = blockIdx.x, h = blockIdx.y, b = blockIdx.z;
    int bh = b * NHEAD + h;
    const float* qb = q + ((size_t)bh * SEQ + qt * 64) * HDIM;
    const float* kb = k + (size_t)bh * SEQ * HDIM;
    const float* vb = v + (size_t)bh * SEQ * HDIM;

    #pragma unroll
    for (int i = 0; i < 4; i++) {
        int slot = tid + i * 256;
        int r  = slot & 63;
        int dc = (slot >> 6) << 2;
        float4 t = *(const float4*)(qb + (size_t)r * HDIM + dc);
        Qt[dc + 0][r] = t.x * 0.125f;
        Qt[dc + 1][r] = t.y * 0.125f;
        Qt[dc + 2][r] = t.z * 0.125f;
        Qt[dc + 3][r] = t.w * 0.125f;
    }

    int tr = tid >> 4, tc = tid & 15;
    int srow = tid >> 2;
    int scol = (tid & 3) << 4;
    float acc[4][4] = {};
    float m_r = -1e30f, l_r = 0.f;

    for (int kt = 0; kt < SEQ / 64; kt++) {
        __syncthreads();
        #pragma unroll
        for (int i = 0; i < 4; i++) {
            int slot = tid + i * 256;
            int r  = slot & 63;
            int dc = (slot >> 6) << 2;
            float4 t = *(const float4*)(kb + (size_t)(kt * 64 + r) * HDIM + dc);
            KVt[dc + 0][r] = t.x;
            KVt[dc + 1][r] = t.y;
            KVt[dc + 2][r] = t.z;
            KVt[dc + 3][r] = t.w;
        }
        __syncthreads();

        float sacc[4][4] = {};
        #pragma unroll 16
        for (int d = 0; d < 64; d++) {
            float4 qa = *(const float4*)&Qt[d][tr << 2];
            float4 kv = *(const float4*)&KVt[d][tc << 2];
            float a[4] = {qa.x, qa.y, qa.z, qa.w};
            float bb[4] = {kv.x, kv.y, kv.z, kv.w};
            #pragma unroll
            for (int i = 0; i < 4; i++)
                #pragma unroll
                for (int j = 0; j < 4; j++)
                    sacc[i][j] = fmaf(a[i], bb[j], sacc[i][j]);
        }
        #pragma unroll
        for (int i = 0; i < 4; i++)
            *(float4*)&Ss[(tr << 2) + i][tc << 2] =
                make_float4(sacc[i][0], sacc[i][1], sacc[i][2], sacc[i][3]);
        __syncthreads();

        #pragma unroll
        for (int i = 0; i < 4; i++) {
            int slot = tid + i * 256;
            int c  = slot >> 4;
            int dc = (slot & 15) << 2;
            *(float4*)&KVt[c][dc] = *(const float4*)(vb + (size_t)(kt * 64 + c) * HDIM + dc);
        }

        float4 sv[4];
        #pragma unroll
        for (int i = 0; i < 4; i++) sv[i] = *(float4*)&Ss[srow][scol + (i << 2)];
        float mx = sv[0].x;
        #pragma unroll
        for (int i = 0; i < 4; i++) {
            mx = fmaxf(mx, sv[i].x); mx = fmaxf(mx, sv[i].y);
            mx = fmaxf(mx, sv[i].z); mx = fmaxf(mx, sv[i].w);
        }
        mx = fmaxf(mx, __shfl_xor_sync(0xffffffffu, mx, 1));
        mx = fmaxf(mx, __shfl_xor_sync(0xffffffffu, mx, 2));
        float m_new = fmaxf(m_r, mx);
        float corr  = __expf(m_r - m_new);
        float sum = 0.f;
        #pragma unroll
        for (int i = 0; i < 4; i++) {
            sv[i].x = __expf(sv[i].x - m_new);
            sv[i].y = __expf(sv[i].y - m_new);
            sv[i].z = __expf(sv[i].z - m_new);
            sv[i].w = __expf(sv[i].w - m_new);
            sum += sv[i].x + sv[i].y + sv[i].z + sv[i].w;
        }
        sum += __shfl_xor_sync(0xffffffffu, sum, 1);
        sum += __shfl_xor_sync(0xffffffffu, sum, 2);
        l_r = l_r * corr + sum;
        m_r = m_new;
        #pragma unroll
        for (int i = 0; i < 4; i++) *(float4*)&Ss[srow][scol + (i << 2)] = sv[i];
        __syncthreads();

        #pragma unroll
        for (int i = 0; i < 4; i++) {
            float ci = __shfl_sync(0xffffffffu, corr, (((tr << 2) + i) & 7) << 2);
            acc[i][0] *= ci; acc[i][1] *= ci; acc[i][2] *= ci; acc[i][3] *= ci;
        }
        #pragma unroll 8
        for (int c = 0; c < 64; c++) {
            float4 vv = *(const float4*)&KVt[c][tc << 2];
            float p0 = Ss[(tr << 2) + 0][c];
            float p1 = Ss[(tr << 2) + 1][c];
            float p2 = Ss[(tr << 2) + 2][c];
            float p3 = Ss[(tr << 2) + 3][c];
            acc[0][0] = fmaf(p0, vv.x, acc[0][0]); acc[0][1] = fmaf(p0, vv.y, acc[0][1]);
            acc[0][2] = fmaf(p0, vv.z, acc[0][2]); acc[0][3] = fmaf(p0, vv.w, acc[0][3]);
            acc[1][0] = fmaf(p1, vv.x, acc[1][0]); acc[1][1] = fmaf(p1, vv.y, acc[1][1]);
            acc[1][2] = fmaf(p1, vv.z, acc[1][2]); acc[1][3] = fmaf(p1, vv.w, acc[1][3]);
            acc[2][0] = fmaf(p2, vv.x, acc[2][0]); acc[2][1] = fmaf(p2, vv.y, acc[2][1]);
            acc[2][2] = fmaf(p2, vv.z, acc[2][2]); acc[2][3] = fmaf(p2, vv.w, acc[2][3]);
            acc[3][0] = fmaf(p3, vv.x, acc[3][0]); acc[3][1] = fmaf(p3, vv.y, acc[3][1]);
            acc[3][2] = fmaf(p3, vv.z, acc[3][2]); acc[3][3] = fmaf(p3, vv.w, acc[3][3]);
        }
    }

    size_t ob = ((size_t)(b * SEQ + qt * 64)) * DIM + h * HDIM + (tc << 2);
    #pragma unroll
    for (int i = 0; i < 4; i++) {
        float li = __shfl_sync(0xffffffffu, l_r, (((tr << 2) + i) & 7) << 2);
        float inv = 1.f / li;
        *(float4*)(out + ob + (size_t)((tr << 2) + i) * DIM) =
            make_float4(acc[i][0] * inv, acc[i][1] * inv, acc[i][2] * inv, acc[i][3] * inv);
    }
}

// ---------------- launcher ----------------
extern "C" void kernel_launch(void* const* d_in, const int* in_sizes, int n_in,
                              void* d_out, int out_size)
{
    const float* x       = (const float*)d_in[0];
    const float* cosb    = (const float*)d_in[1];
    const float* sinb    = (const float*)d_in[2];
    const float* c       = (const float*)d_in[3];
    const float* norm1_w = (const float*)d_in[4];
    const float* Wqkv    = (const float*)d_in[5];
    const float* Wout    = (const float*)d_in[6];
    const float* q_norm_w= (const float*)d_in[7];
    const float* k_norm_w= (const float*)d_in[8];
    const float* norm2_w = (const float*)d_in[9];
    const float* W1      = (const float*)d_in[10];
    const float* b1      = (const float*)d_in[11];
    const float* W2      = (const float*)d_in[12];
    const float* b2      = (const float*)d_in[13];
    const float* ada_W   = (const float*)d_in[14];
    const float* ada_b   = (const float*)d_in[15];
    float* out = (float*)d_out;

    float *mod, *xn, *qkv, *qb, *kb, *vb, *attn, *x1, *hb;
    cudaGetSymbolAddress((void**)&mod,  g_mod);
    cudaGetSymbolAddress((void**)&xn,   g_xn);
    cudaGetSymbolAddress((void**)&qkv,  g_qkv);
    cudaGetSymbolAddress((void**)&qb,   g_q);
    cudaGetSymbolAddress((void**)&kb,   g_k);
    cudaGetSymbolAddress((void**)&vb,   g_v);
    cudaGetSymbolAddress((void**)&attn, g_attn);
    cudaGetSymbolAddress((void**)&x1,   g_x1);
    cudaGetSymbolAddress((void**)&hb,   g_h);

    // 1. adaLN modulation
    mod_kernel<<<dim3(MODD / 256, BATCH), 256>>>(c, ada_W, ada_b, mod);
    // 2. LN1 + modulate
    ln_mod_kernel<<<NTOK, 256>>>(x, norm1_w, mod, 0, 1024, xn);
    // 3. QKV GEMM (tf32 MMA)
    mma_gemm<0><<<dim3(3 * DIM / BN, NTOK / BM), 256>>>(
        xn, Wqkv, qkv, NTOK, 3 * DIM, DIM, nullptr, nullptr, nullptr, 0);
    // 4. RMSNorm + RoPE
    qkv_prep_kernel<<<(BATCH * SEQ * NHEAD) / 8, 256>>>(
        qkv, q_norm_w, k_norm_w, cosb, sinb, qb, kb, vb);
    // 5. attention
    attn_kernel<<<dim3(SEQ / 64, NHEAD, BATCH), 256>>>(qb, kb, vb, attn);
    // 6. out proj + gate + residual  -> x1
    mma_gemm<2><<<dim3(DIM / BN, NTOK / BM), 256>>>(
        attn, Wout, x1, NTOK, DIM, DIM, nullptr, x, mod, 2048);
    // 7. LN2 + modulate
    ln_mod_kernel<<<NTOK, 256>>>(x1, norm2_w, mod, 3072, 4096, xn);
    // 8. MLP up + GELU
    mma_gemm<1><<<dim3(DFF / BN, NTOK / BM), 256>>>(
        xn, W1, hb, NTOK, DFF, DIM, b1, nullptr, nullptr, 0);
    // 9. MLP down + gate + residual -> out
    mma_gemm<2><<<dim3(DIM / BN, NTOK / BM), 256>>>(
        hb, W2, out, NTOK, DIM, DFF, b2, x1, mod, 5120);
}

// round 9
// speedup vs baseline: 2.5827x; 1.5758x over previous
#include <cuda_runtime.h>
#include <cuda_bf16.h>
#include <cstdint>

// Problem constants
#define BATCH 4
#define SEQ   2048
#define DIM   1024
#define NHEAD 16
#define HDIM  64
#define DFF   4096
#define NTOK  (BATCH*SEQ)          // 8192
#define MODD  6144                 // 6*DIM

// ---------------- scratch (__device__ globals; allocation-free) ----------------
__device__ float g_mod [BATCH*MODD];
__device__ float g_xn  [NTOK*DIM];
__device__ float g_qkv [NTOK*3*DIM];
__device__ float g_q   [BATCH*NHEAD*SEQ*HDIM];
__device__ float g_k   [BATCH*NHEAD*SEQ*HDIM];
__device__ float g_v   [BATCH*NHEAD*SEQ*HDIM];
__device__ float g_attn[NTOK*DIM];
__device__ float g_x1  [NTOK*DIM];
__device__ float g_h   [NTOK*DFF];

// ---------------- adaLN modulation: mod = c @ ada_W + ada_b ----------------
__global__ void mod_kernel(const float* __restrict__ c,
                           const float* __restrict__ adaW,
                           const float* __restrict__ adab,
                           float* __restrict__ mod)
{
    int j = blockIdx.x * 256 + threadIdx.x;
    int b = blockIdx.y;
    const float* crow = c + b * 1024;
    float acc = adab[j];
    #pragma unroll 4
    for (int k = 0; k < 1024; k++)
        acc = fmaf(__ldg(crow + k), __ldg(adaW + (size_t)k * MODD + j), acc);
    mod[b * MODD + j] = acc;
}

// ---------------- LayerNorm + adaLN modulate ----------------
__global__ void ln_mod_kernel(const float* __restrict__ x,
                              const float* __restrict__ w,
                              const float* __restrict__ mod,
                              int sh_off, int sc_off,
                              float* __restrict__ out)
{
    __shared__ float red[16];
    __shared__ float stats[2];
    int t = blockIdx.x;
    int b = t >> 11;
    const float4* xr = (const float4*)(x + (size_t)t * DIM);
    float4 xv = xr[threadIdx.x];

    float s  = xv.x + xv.y + xv.z + xv.w;
    float sq = xv.x*xv.x + xv.y*xv.y + xv.z*xv.z + xv.w*xv.w;
    #pragma unroll
    for (int o = 16; o; o >>= 1) {
        s  += __shfl_down_sync(0xffffffffu, s,  o);
        sq += __shfl_down_sync(0xffffffffu, sq, o);
    }
    int wid = threadIdx.x >> 5, lane = threadIdx.x & 31;
    if (lane == 0) { red[wid] = s; red[wid + 8] = sq; }
    __syncthreads();
    if (threadIdx.x == 0) {
        float ts = 0.f, tq = 0.f;
        #pragma unroll
        for (int i = 0; i < 8; i++) { ts += red[i]; tq += red[i + 8]; }
        float mu  = ts * (1.f / DIM);
        float var = tq * (1.f / DIM) - mu * mu;
        stats[0] = mu;
        stats[1] = rsqrtf(var + 1e-5f);
    }
    __syncthreads();
    float mu = stats[0], rstd = stats[1];

    const float* modb = mod + b * MODD;
    float4 wv = ((const float4*)w)[threadIdx.x];
    float4 sc = ((const float4*)(modb + sc_off))[threadIdx.x];
    float4 sh = ((const float4*)(modb + sh_off))[threadIdx.x];
    float4 o;
    o.x = (xv.x - mu) * rstd * wv.x * (1.f + sc.x) + sh.x;
    o.y = (xv.y - mu) * rstd * wv.y * (1.f + sc.y) + sh.y;
    o.z = (xv.z - mu) * rstd * wv.z * (1.f + sc.z) + sh.z;
    o.w = (xv.w - mu) * rstd * wv.w * (1.f + sc.w) + sh.w;
    ((float4*)(out + (size_t)t * DIM))[threadIdx.x] = o;
}

// ---------------- tf32 MMA helpers ----------------
__device__ __forceinline__ uint32_t f2tf32(float f)
{
    uint32_t u;
    asm("cvt.rna.tf32.f32 %0, %1;" : "=r"(u) : "f"(f));
    return u;
}

__device__ __forceinline__ void mma_tf32(float* c,
                                         uint32_t a0, uint32_t a1, uint32_t a2, uint32_t a3,
                                         uint32_t b0, uint32_t b1)
{
    asm volatile("mma.sync.aligned.m16n8k8.row.col.f32.tf32.tf32.f32 "
                 "{%0,%1,%2,%3}, {%4,%5,%6,%7}, {%8,%9}, {%0,%1,%2,%3};"
                 : "+f"(c[0]), "+f"(c[1]), "+f"(c[2]), "+f"(c[3])
                 : "r"(a0), "r"(a1), "r"(a2), "r"(a3), "r"(b0), "r"(b1));
}

__device__ __forceinline__ float gelu_tanh(float x)
{
    float x3 = x * x * x;
    return 0.5f * x * (1.f + tanhf(0.7978845608028654f * (x + 0.044715f * x3)));
}

// ---------------- tf32 tensor-core GEMM, 128x128 block, BK=16 ----------------
#define BM 128
#define BN 128
#define BK 16
#define ASTR 20
#define BSTR 136

template<int MODE>
__global__ __launch_bounds__(256)
void mma_gemm(const float* __restrict__ A, const float* __restrict__ Bm,
              float* __restrict__ C, int M, int N, int K,
              const float* __restrict__ bias,
              const float* __restrict__ res,
              const float* __restrict__ mod, int goff)
{
    __shared__ uint32_t As[2][BM * ASTR];
    __shared__ uint32_t Bs[2][BK * BSTR];

    const int tid  = threadIdx.x;
    const int lane = tid & 31, warp = tid >> 5;
    const int g = lane >> 2, tg = lane & 3;
    const int warpM = warp & 1, warpN = warp >> 1;
    const int rowBase = blockIdx.y << 7, colBase = blockIdx.x << 7;

    const int ar0 = tid >> 2, ak0 = (tid & 3) << 2;
    const int br0 = tid >> 5, bn0 = (tid & 31) << 2;

    const float* Ag = A + (size_t)rowBase * K;

    float4 stA[2], stB[2];
    #pragma unroll
    for (int i = 0; i < 2; i++) {
        stA[i] = *(const float4*)(Ag + (size_t)(ar0 + i * 64) * K + ak0);
        stB[i] = *(const float4*)(Bm + (size_t)(br0 + i * 8) * N + colBase + bn0);
    }

    auto sts = [&](int buf) {
        #pragma unroll
        for (int i = 0; i < 2; i++) {
            uint32_t* ap = &As[buf][(ar0 + i * 64) * ASTR + ak0];
            ap[0] = f2tf32(stA[i].x); ap[1] = f2tf32(stA[i].y);
            ap[2] = f2tf32(stA[i].z); ap[3] = f2tf32(stA[i].w);
            uint4 bq;
            bq.x = f2tf32(stB[i].x); bq.y = f2tf32(stB[i].y);
            bq.z = f2tf32(stB[i].z); bq.w = f2tf32(stB[i].w);
            *(uint4*)&Bs[buf][(br0 + i * 8) * BSTR + bn0] = bq;
        }
    };
    sts(0);
    __syncthreads();

    float acc[4][4][4] = {};
    const int ntiles = K >> 4;

    for (int kt = 0; kt < ntiles; kt++) {
        const int buf = kt & 1;
        if (kt + 1 < ntiles) {
            #pragma unroll
            for (int i = 0; i < 2; i++) {
                stA[i] = *(const float4*)(Ag + (size_t)(ar0 + i * 64) * K + (kt + 1) * BK + ak0);
                stB[i] = *(const float4*)(Bm + (size_t)((kt + 1) * BK + br0 + i * 8) * N + colBase + bn0);
            }
        }
        #pragma unroll
        for (int ks = 0; ks < 2; ks++) {
            const int k0 = ks << 3;
            uint32_t af[4][4], bf[4][2];
            #pragma unroll
            for (int mt = 0; mt < 4; mt++) {
                int m = (warpM << 6) + (mt << 4) + g;
                const uint32_t* asb = &As[buf][0];
                af[mt][0] = asb[(size_t)m * ASTR + k0 + tg];
                af[mt][1] = asb[(size_t)(m + 8) * ASTR + k0 + tg];
                af[mt][2] = asb[(size_t)m * ASTR + k0 + tg + 4];
                af[mt][3] = asb[(size_t)(m + 8) * ASTR + k0 + tg + 4];
            }
            #pragma unroll
            for (int nt = 0; nt < 4; nt++) {
                int n = (warpN << 5) + (nt << 3) + g;
                bf[nt][0] = Bs[buf][(k0 + tg) * BSTR + n];
                bf[nt][1] = Bs[buf][(k0 + tg + 4) * BSTR + n];
            }
            #pragma unroll
            for (int mt = 0; mt < 4; mt++)
                #pragma unroll
                for (int nt = 0; nt < 4; nt++)
                    mma_tf32(acc[mt][nt],
                             af[mt][0], af[mt][1], af[mt][2], af[mt][3],
                             bf[nt][0], bf[nt][1]);
        }
        if (kt + 1 < ntiles) sts(buf ^ 1);
        __syncthreads();
    }

    const int bidx = rowBase >> 11;
    #pragma unroll
    for (int nt = 0; nt < 4; nt++) {
        int col = colBase + (warpN << 5) + (nt << 3) + (tg << 1);
        float gv0 = 0.f, gv1 = 0.f, bv0 = 0.f, bv1 = 0.f;
        if (MODE == 2) {
            const float* gm = mod + bidx * MODD + goff;
            gv0 = gm[col]; gv1 = gm[col + 1];
        }
        if (MODE >= 1 && bias) { bv0 = bias[col]; bv1 = bias[col + 1]; }
        #pragma unroll
        for (int mt = 0; mt < 4; mt++) {
            int r0 = rowBase + (warpM << 6) + (mt << 4) + g;
            #pragma unroll
            for (int half = 0; half < 2; half++) {
                int r = r0 + half * 8;
                float v0 = acc[mt][nt][half * 2];
                float v1 = acc[mt][nt][half * 2 + 1];
                size_t off = (size_t)r * N + col;
                if (MODE == 1) {
                    v0 = gelu_tanh(v0 + bv0);
                    v1 = gelu_tanh(v1 + bv1);
                } else if (MODE == 2) {
                    float2 rv = *(const float2*)(res + off);
                    v0 = rv.x + gv0 * (v0 + bv0);
                    v1 = rv.y + gv1 * (v1 + bv1);
                }
                *(float2*)(C + off) = make_float2(v0, v1);
            }
        }
    }
}

// ---------------- RMSNorm + RoPE for q,k; reshape v ----------------
__global__ void qkv_prep_kernel(const float* __restrict__ qkv,
                                const float* __restrict__ qw,
                                const float* __restrict__ kw,
                                const float* __restrict__ cosb,
                                const float* __restrict__ sinb,
                                float* __restrict__ qo,
                                float* __restrict__ ko,
                                float* __restrict__ vo)
{
    int gid  = blockIdx.x * blockDim.x + threadIdx.x;
    int lane = gid & 31;
    int widx = gid >> 5;
    int h = widx & 15;
    int s = (widx >> 4) & 2047;
    int b = widx >> 15;

    const float* base = qkv + (size_t)(b * SEQ + s) * (3 * DIM) + h * HDIM;
    float q1 = base[lane],            q2 = base[lane + 32];
    float k1 = base[DIM + lane],      k2 = base[DIM + lane + 32];
    float v1 = base[2 * DIM + lane],  v2 = base[2 * DIM + lane + 32];

    float ssq = q1 * q1 + q2 * q2;
    float ssk = k1 * k1 + k2 * k2;
    #pragma unroll
    for (int o = 16; o; o >>= 1) {
        ssq += __shfl_xor_sync(0xffffffffu, ssq, o);
        ssk += __shfl_xor_sync(0xffffffffu, ssk, o);
    }
    float rq = rsqrtf(ssq * (1.f / HDIM) + 1e-6f);
    float rk = rsqrtf(ssk * (1.f / HDIM) + 1e-6f);
    q1 *= rq * qw[lane];  q2 *= rq * qw[lane + 32];
    k1 *= rk * kw[lane];  k2 *= rk * kw[lane + 32];

    float c1 = cosb[s * HDIM + lane], c2 = cosb[s * HDIM + lane + 32];
    float s1 = sinb[s * HDIM + lane], s2 = sinb[s * HDIM + lane + 32];
    float oq1 = q1 * c1 - q2 * s1;
    float oq2 = q2 * c2 + q1 * s2;
    float ok1 = k1 * c1 - k2 * s1;
    float ok2 = k2 * c2 + k1 * s2;

    size_t off = ((size_t)(b * NHEAD + h) * SEQ + s) * HDIM;
    qo[off + lane] = oq1; qo[off + lane + 32] = oq2;
    ko[off + lane] = ok1; ko[off + lane + 32] = ok2;
    vo[off + lane] = v1;  vo[off + lane + 32] = v2;
}

// ---------------- Flash attention (tf32 MMA): 128 q-rows/block, 32-key tiles ----------------
// 8 warps x 16 q-rows each: every warp owns full rows -> softmax within lane-quad.
__global__ __launch_bounds__(256, 2)
void attn_mma_kernel(const float* __restrict__ q, const float* __restrict__ k,
                     const float* __restrict__ v, float* __restrict__ out)
{
    __shared__ uint32_t Ks[32][68];   // [key][d], bank = 4g+tg for S b-frags
    __shared__ uint32_t Vs[32][72];   // [key][d], bank = 8tg+g for PV b-frags
    __shared__ uint32_t Ps[128][36];  // per-warp-private P rows (tf32)

    const int tid  = threadIdx.x;
    const int warp = tid >> 5, lane = tid & 31;
    const int g = lane >> 2, tg = lane & 3;
    const int qt = blockIdx.x, h = blockIdx.y, b = blockIdx.z;
    const int bh = b * NHEAD + h;
    const float* kb = k + (size_t)bh * SEQ * HDIM;
    const float* vb = v + (size_t)bh * SEQ * HDIM;

    // preload Q as A-fragments (rows warp*16+{g,g+8}), pre-scaled by 1/8
    const float* qg = q + ((size_t)bh * SEQ + qt * 128 + warp * 16) * HDIM;
    uint32_t qa[8][4];
    #pragma unroll
    for (int kk = 0; kk < 8; kk++) {
        qa[kk][0] = f2tf32(0.125f * qg[(size_t)g       * HDIM + kk * 8 + tg]);
        qa[kk][1] = f2tf32(0.125f * qg[(size_t)(g + 8) * HDIM + kk * 8 + tg]);
        qa[kk][2] = f2tf32(0.125f * qg[(size_t)g       * HDIM + kk * 8 + tg + 4]);
        qa[kk][3] = f2tf32(0.125f * qg[(size_t)(g + 8) * HDIM + kk * 8 + tg + 4]);
    }

    float o[8][4] = {};
    float m0 = -1e30f, m1 = -1e30f, l0 = 0.f, l1 = 0.f;

    const int lr = tid >> 4;          // 0..15 (load row)
    const int lc = (tid & 15) << 2;   // 0..60 (load col)
    const int pr = warp * 16;         // P row base

    for (int kt = 0; kt < SEQ / 32; kt++) {
        __syncthreads();   // all warps done with previous Ks/Vs
        // cooperative K/V tile load, tf32 convert, uint4 STS
        #pragma unroll
        for (int i = 0; i < 2; i++) {
            int r = lr + i * 16;
            float4 kf = *(const float4*)(kb + (size_t)(kt * 32 + r) * HDIM + lc);
            uint4 kq; kq.x = f2tf32(kf.x); kq.y = f2tf32(kf.y);
            kq.z = f2tf32(kf.z); kq.w = f2tf32(kf.w);
            *(uint4*)&Ks[r][lc] = kq;
            float4 vf = *(const float4*)(vb + (size_t)(kt * 32 + r) * HDIM + lc);
            uint4 vq; vq.x = f2tf32(vf.x); vq.y = f2tf32(vf.y);
            vq.z = f2tf32(vf.z); vq.w = f2tf32(vf.w);
            *(uint4*)&Vs[r][lc] = vq;
        }
        __syncthreads();

        // S = Q K^T : 16 rows x 32 keys per warp
        float s[4][4] = {};
        #pragma unroll
        for (int kk = 0; kk < 8; kk++) {
            #pragma unroll
            for (int nt = 0; nt < 4; nt++) {
                uint32_t b0 = Ks[nt * 8 + g][kk * 8 + tg];
                uint32_t b1 = Ks[nt * 8 + g][kk * 8 + tg + 4];
                mma_tf32(s[nt], qa[kk][0], qa[kk][1], qa[kk][2], qa[kk][3], b0, b1);
            }
        }

        // online softmax (rows g and g+8)
        float mx0 = -1e30f, mx1 = -1e30f;
        #pragma unroll
        for (int nt = 0; nt < 4; nt++) {
            mx0 = fmaxf(mx0, fmaxf(s[nt][0], s[nt][1]));
            mx1 = fmaxf(mx1, fmaxf(s[nt][2], s[nt][3]));
        }
        mx0 = fmaxf(mx0, __shfl_xor_sync(0xffffffffu, mx0, 1));
        mx0 = fmaxf(mx0, __shfl_xor_sync(0xffffffffu, mx0, 2));
        mx1 = fmaxf(mx1, __shfl_xor_sync(0xffffffffu, mx1, 1));
        mx1 = fmaxf(mx1, __shfl_xor_sync(0xffffffffu, mx1, 2));
        float nm0 = fmaxf(m0, mx0), nm1 = fmaxf(m1, mx1);
        float c0 = __expf(m0 - nm0), c1 = __expf(m1 - nm1);
        float sum0 = 0.f, sum1 = 0.f;
        #pragma unroll
        for (int nt = 0; nt < 4; nt++) {
            s[nt][0] = __expf(s[nt][0] - nm0);
            s[nt][1] = __expf(s[nt][1] - nm0);
            s[nt][2] = __expf(s[nt][2] - nm1);
            s[nt][3] = __expf(s[nt][3] - nm1);
            sum0 += s[nt][0] + s[nt][1];
            sum1 += s[nt][2] + s[nt][3];
        }
        sum0 += __shfl_xor_sync(0xffffffffu, sum0, 1);
        sum0 += __shfl_xor_sync(0xffffffffu, sum0, 2);
        sum1 += __shfl_xor_sync(0xffffffffu, sum1, 1);
        sum1 += __shfl_xor_sync(0xffffffffu, sum1, 2);
        l0 = l0 * c0 + sum0;
        l1 = l1 * c1 + sum1;
        m0 = nm0; m1 = nm1;

        // rescale O accumulators
        #pragma unroll
        for (int nt = 0; nt < 8; nt++) {
            o[nt][0] *= c0; o[nt][1] *= c0;
            o[nt][2] *= c1; o[nt][3] *= c1;
        }

        // write P (tf32) to per-warp-private smem rows
        #pragma unroll
        for (int nt = 0; nt < 4; nt++) {
            Ps[pr + g][nt * 8 + 2 * tg]         = f2tf32(s[nt][0]);
            Ps[pr + g][nt * 8 + 2 * tg + 1]     = f2tf32(s[nt][1]);
            Ps[pr + g + 8][nt * 8 + 2 * tg]     = f2tf32(s[nt][2]);
            Ps[pr + g + 8][nt * 8 + 2 * tg + 1] = f2tf32(s[nt][3]);
        }
        __syncwarp();

        // O += P V
        #pragma unroll
        for (int kk = 0; kk < 4; kk++) {
            uint32_t a0 = Ps[pr + g][kk * 8 + tg];
            uint32_t a1 = Ps[pr + g + 8][kk * 8 + tg];
            uint32_t a2 = Ps[pr + g][kk * 8 + tg + 4];
            uint32_t a3 = Ps[pr + g + 8][kk * 8 + tg + 4];
            #pragma unroll
            for (int nt = 0; nt < 8; nt++) {
                uint32_t b0 = Vs[kk * 8 + tg][nt * 8 + g];
                uint32_t b1 = Vs[kk * 8 + tg + 4][nt * 8 + g];
                mma_tf32(o[nt], a0, a1, a2, a3, b0, b1);
            }
        }
    }

    // epilogue: normalize, write [B,S,H*HD]
    float inv0 = 1.f / l0, inv1 = 1.f / l1;
    size_t rbase = (size_t)(b * SEQ + qt * 128 + warp * 16);
    #pragma unroll
    for (int nt = 0; nt < 8; nt++) {
        int col = h * HDIM + nt * 8 + 2 * tg;
        *(float2*)(out + (rbase + g) * DIM + col) =
            make_float2(o[nt][0] * inv0, o[nt][1] * inv0);
        *(float2*)(out + (rbase + g + 8) * DIM + col) =
            make_float2(o[nt][2] * inv1, o[nt][3] * inv1);
    }
}

// ---------------- launcher ----------------
extern "C" void kernel_launch(void* const* d_in, const int* in_sizes, int n_in,
                              void* d_out, int out_size)
{
    const float* x       = (const float*)d_in[0];
    const float* cosb    = (const float*)d_in[1];
    const float* sinb    = (const float*)d_in[2];
    const float* c       = (const float*)d_in[3];
    const float* norm1_w = (const float*)d_in[4];
    const float* Wqkv    = (const float*)d_in[5];
    const float* Wout    = (const float*)d_in[6];
    const float* q_norm_w= (const float*)d_in[7];
    const float* k_norm_w= (const float*)d_in[8];
    const float* norm2_w = (const float*)d_in[9];
    const float* W1      = (const float*)d_in[10];
    const float* b1      = (const float*)d_in[11];
    const float* W2      = (const float*)d_in[12];
    const float* b2      = (const float*)d_in[13];
    const float* ada_W   = (const float*)d_in[14];
    const float* ada_b   = (const float*)d_in[15];
    float* out = (float*)d_out;

    float *mod, *xn, *qkv, *qb, *kb, *vb, *attn, *x1, *hb;
    cudaGetSymbolAddress((void**)&mod,  g_mod);
    cudaGetSymbolAddress((void**)&xn,   g_xn);
    cudaGetSymbolAddress((void**)&qkv,  g_qkv);
    cudaGetSymbolAddress((void**)&qb,   g_q);
    cudaGetSymbolAddress((void**)&kb,   g_k);
    cudaGetSymbolAddress((void**)&vb,   g_v);
    cudaGetSymbolAddress((void**)&attn, g_attn);
    cudaGetSymbolAddress((void**)&x1,   g_x1);
    cudaGetSymbolAddress((void**)&hb,   g_h);

    // 1. adaLN modulation
    mod_kernel<<<dim3(MODD / 256, BATCH), 256>>>(c, ada_W, ada_b, mod);
    // 2. LN1 + modulate
    ln_mod_kernel<<<NTOK, 256>>>(x, norm1_w, mod, 0, 1024, xn);
    // 3. QKV GEMM (tf32 MMA)
    mma_gemm<0><<<dim3(3 * DIM / BN, NTOK / BM), 256>>>(
        xn, Wqkv, qkv, NTOK, 3 * DIM, DIM, nullptr, nullptr, nullptr, 0);
    // 4. RMSNorm + RoPE
    qkv_prep_kernel<<<(BATCH * SEQ * NHEAD) / 8, 256>>>(
        qkv, q_norm_w, k_norm_w, cosb, sinb, qb, kb, vb);
    // 5. attention (tf32 MMA flash)
    attn_mma_kernel<<<dim3(SEQ / 128, NHEAD, BATCH), 256>>>(qb, kb, vb, attn);
    // 6. out proj + gate + residual  -> x1
    mma_gemm<2><<<dim3(DIM / BN, NTOK / BM), 256>>>(
        attn, Wout, x1, NTOK, DIM, DIM, nullptr, x, mod, 2048);
    // 7. LN2 + modulate
    ln_mod_kernel<<<NTOK, 256>>>(x1, norm2_w, mod, 3072, 4096, xn);
    // 8. MLP up + GELU
    mma_gemm<1><<<dim3(DFF / BN, NTOK / BM), 256>>>(
        xn, W1, hb, NTOK, DFF, DIM, b1, nullptr, nullptr, 0);
    // 9. MLP down + gate + residual -> out
    mma_gemm<2><<<dim3(DIM / BN, NTOK / BM), 256>>>(
        hb, W2, out, NTOK, DIM, DFF, b2, x1, mod, 5120);
}

// round 12
// speedup vs baseline: 3.1264x; 1.2105x over previous
#include <cuda_runtime.h>
#include <cuda_bf16.h>
#include <cstdint>

// Problem constants
#define BATCH 4
#define SEQ   2048
#define DIM   1024
#define NHEAD 16
#define HDIM  64
#define DFF   4096
#define NTOK  (BATCH*SEQ)          // 8192
#define MODD  6144                 // 6*DIM

// ---------------- scratch (__device__ globals; allocation-free) ----------------
__device__ float g_mod [BATCH*MODD];
__device__ float g_xn  [NTOK*DIM];
__device__ float g_qkv [NTOK*3*DIM];
__device__ float g_q   [BATCH*NHEAD*SEQ*HDIM];
__device__ float g_k   [BATCH*NHEAD*SEQ*HDIM];
__device__ float g_v   [BATCH*NHEAD*SEQ*HDIM];
__device__ float g_attn[NTOK*DIM];
__device__ float g_x1  [NTOK*DIM];
__device__ float g_h   [NTOK*DFF];
// tf32-rounded weight copies
__device__ float g_wqkv[DIM*3*DIM];
__device__ float g_wout[DIM*DIM];
__device__ float g_w1  [DIM*DFF];
__device__ float g_w2  [DFF*DIM];

// ---------------- tf32 helpers ----------------
__device__ __forceinline__ uint32_t f2tf32(float f)
{
    uint32_t u;
    asm("cvt.rna.tf32.f32 %0, %1;" : "=r"(u) : "f"(f));
    return u;
}
__device__ __forceinline__ float roundtf32(float f)
{
    return __uint_as_float(f2tf32(f));
}

__device__ __forceinline__ void mma_tf32(float* c,
                                         uint32_t a0, uint32_t a1, uint32_t a2, uint32_t a3,
                                         uint32_t b0, uint32_t b1)
{
    asm volatile("mma.sync.aligned.m16n8k8.row.col.f32.tf32.tf32.f32 "
                 "{%0,%1,%2,%3}, {%4,%5,%6,%7}, {%8,%9}, {%0,%1,%2,%3};"
                 : "+f"(c[0]), "+f"(c[1]), "+f"(c[2]), "+f"(c[3])
                 : "r"(a0), "r"(a1), "r"(a2), "r"(a3), "r"(b0), "r"(b1));
}

__device__ __forceinline__ uint32_t smem_u32(const void* p)
{
    return (uint32_t)__cvta_generic_to_shared(p);
}

__device__ __forceinline__ void cpasync16(uint32_t dst, const void* src)
{
    asm volatile("cp.async.cg.shared.global [%0], [%1], 16;" :: "r"(dst), "l"(src));
}

__device__ __forceinline__ void ldmatrix_x4(uint32_t* r, uint32_t addr)
{
    asm volatile("ldmatrix.sync.aligned.m8n8.x4.shared.b16 {%0,%1,%2,%3}, [%4];"
                 : "=r"(r[0]), "=r"(r[1]), "=r"(r[2]), "=r"(r[3]) : "r"(addr));
}

__device__ __forceinline__ float gelu_tanh(float x)
{
    float x3 = x * x * x;
    return 0.5f * x * (1.f + tanhf(0.7978845608028654f * (x + 0.044715f * x3)));
}

// ---------------- weight rounding (fp32 -> tf32 bit pattern) ----------------
__global__ void round_copy_kernel(const float* __restrict__ src,
                                  float* __restrict__ dst, int n4)
{
    int i = blockIdx.x * 256 + threadIdx.x;
    if (i < n4) {
        float4 v = ((const float4*)src)[i];
        v.x = roundtf32(v.x); v.y = roundtf32(v.y);
        v.z = roundtf32(v.z); v.w = roundtf32(v.w);
        ((float4*)dst)[i] = v;
    }
}

// ---------------- adaLN modulation: mod = c @ ada_W + ada_b ----------------
__global__ void mod_kernel(const float* __restrict__ c,
                           const float* __restrict__ adaW,
                           const float* __restrict__ adab,
                           float* __restrict__ mod)
{
    int j = blockIdx.x * 256 + threadIdx.x;
    int b = blockIdx.y;
    const float* crow = c + b * 1024;
    float acc = adab[j];
    #pragma unroll 4
    for (int k = 0; k < 1024; k++)
        acc = fmaf(__ldg(crow + k), __ldg(adaW + (size_t)k * MODD + j), acc);
    mod[b * MODD + j] = acc;
}

// ---------------- LayerNorm + adaLN modulate (output tf32-rounded) ----------------
__global__ void ln_mod_kernel(const float* __restrict__ x,
                              const float* __restrict__ w,
                              const float* __restrict__ mod,
                              int sh_off, int sc_off,
                              float* __restrict__ out)
{
    __shared__ float red[16];
    __shared__ float stats[2];
    int t = blockIdx.x;
    int b = t >> 11;
    const float4* xr = (const float4*)(x + (size_t)t * DIM);
    float4 xv = xr[threadIdx.x];

    float s  = xv.x + xv.y + xv.z + xv.w;
    float sq = xv.x*xv.x + xv.y*xv.y + xv.z*xv.z + xv.w*xv.w;
    #pragma unroll
    for (int o = 16; o; o >>= 1) {
        s  += __shfl_down_sync(0xffffffffu, s,  o);
        sq += __shfl_down_sync(0xffffffffu, sq, o);
    }
    int wid = threadIdx.x >> 5, lane = threadIdx.x & 31;
    if (lane == 0) { red[wid] = s; red[wid + 8] = sq; }
    __syncthreads();
    if (threadIdx.x == 0) {
        float ts = 0.f, tq = 0.f;
        #pragma unroll
        for (int i = 0; i < 8; i++) { ts += red[i]; tq += red[i + 8]; }
        float mu  = ts * (1.f / DIM);
        float var = tq * (1.f / DIM) - mu * mu;
        stats[0] = mu;
        stats[1] = rsqrtf(var + 1e-5f);
    }
    __syncthreads();
    float mu = stats[0], rstd = stats[1];

    const float* modb = mod + b * MODD;
    float4 wv = ((const float4*)w)[threadIdx.x];
    float4 sc = ((const float4*)(modb + sc_off))[threadIdx.x];
    float4 sh = ((const float4*)(modb + sh_off))[threadIdx.x];
    float4 o;
    o.x = roundtf32((xv.x - mu) * rstd * wv.x * (1.f + sc.x) + sh.x);
    o.y = roundtf32((xv.y - mu) * rstd * wv.y * (1.f + sc.y) + sh.y);
    o.z = roundtf32((xv.z - mu) * rstd * wv.z * (1.f + sc.z) + sh.z);
    o.w = roundtf32((xv.w - mu) * rstd * wv.w * (1.f + sc.w) + sh.w);
    ((float4*)(out + (size_t)t * DIM))[threadIdx.x] = o;
}

// ---------------- tf32 tensor-core GEMM, 128x128 block, BK=16, cp.async + ldmatrix ----------------
// Inputs A and B must already be tf32-rounded bit patterns.
// MODE 0: C = A@B
// MODE 1: C = roundtf32(gelu_tanh(A@B + bias))
// MODE 2: C = res + g[b,col] * (A@B (+ bias))
#define BM 128
#define BN 128
#define BK 16
#define ASTR 20
#define BSTR 136

template<int MODE>
__global__ __launch_bounds__(256, 2)
void mma_gemm(const float* __restrict__ A, const float* __restrict__ Bm,
              float* __restrict__ C, int M, int N, int K,
              const float* __restrict__ bias,
              const float* __restrict__ res,
              const float* __restrict__ mod, int goff)
{
    __shared__ __align__(16) float As[2][BM * ASTR];   // [m][k], stride 20
    __shared__ __align__(16) float Bs[2][BK * BSTR];   // [k][n], stride 136

    const int tid  = threadIdx.x;
    const int lane = tid & 31, warp = tid >> 5;
    const int g = lane >> 2, tg = lane & 3;
    const int warpM = warp & 1, warpN = warp >> 1;
    const int rowBase = blockIdx.y << 7, colBase = blockIdx.x << 7;

    const int ar0 = tid >> 2, ak0 = (tid & 3) << 2;
    const int br0 = tid >> 5, bn0 = (tid & 31) << 2;

    const float* Ag = A + (size_t)rowBase * K;

    // ldmatrix lane offset within A tile (8x4-tf32 quad layout)
    const int laneRow = (lane & 7) + (lane & 8);
    const int laneCol = (lane & 16) >> 2;
    const int aLaneOff = laneRow * ASTR + laneCol;

    auto issue = [&](int kt, int buf) {
        #pragma unroll
        for (int i = 0; i < 2; i++) {
            cpasync16(smem_u32(&As[buf][(ar0 + i * 64) * ASTR + ak0]),
                      Ag + (size_t)(ar0 + i * 64) * K + kt * BK + ak0);
            cpasync16(smem_u32(&Bs[buf][(br0 + i * 8) * BSTR + bn0]),
                      Bm + (size_t)(kt * BK + br0 + i * 8) * N + colBase + bn0);
        }
        asm volatile("cp.async.commit_group;");
    };

    issue(0, 0);

    float acc[4][4][4] = {};
    const int ntiles = K >> 4;

    for (int kt = 0; kt < ntiles; kt++) {
        const int buf = kt & 1;
        if (kt + 1 < ntiles) {
            issue(kt + 1, buf ^ 1);
            asm volatile("cp.async.wait_group 1;");
        } else {
            asm volatile("cp.async.wait_group 0;");
        }
        __syncthreads();

        #pragma unroll
        for (int ks = 0; ks < 2; ks++) {
            const int k0 = ks << 3;
            uint32_t af[4][4], bf[4][2];
            #pragma unroll
            for (int mt = 0; mt < 4; mt++) {
                int m0 = (warpM << 6) + (mt << 4);
                ldmatrix_x4(af[mt], smem_u32(&As[buf][m0 * ASTR + k0 + aLaneOff]));
            }
            #pragma unroll
            for (int nt = 0; nt < 4; nt++) {
                int n = (warpN << 5) + (nt << 3) + g;
                bf[nt][0] = __float_as_uint(Bs[buf][(k0 + tg) * BSTR + n]);
                bf[nt][1] = __float_as_uint(Bs[buf][(k0 + tg + 4) * BSTR + n]);
            }
            #pragma unroll
            for (int mt = 0; mt < 4; mt++)
                #pragma unroll
                for (int nt = 0; nt < 4; nt++)
                    mma_tf32(acc[mt][nt],
                             af[mt][0], af[mt][1], af[mt][2], af[mt][3],
                             bf[nt][0], bf[nt][1]);
        }
        __syncthreads();
    }

    // epilogue
    const int bidx = rowBase >> 11;
    #pragma unroll
    for (int nt = 0; nt < 4; nt++) {
        int col = colBase + (warpN << 5) + (nt << 3) + (tg << 1);
        float gv0 = 0.f, gv1 = 0.f, bv0 = 0.f, bv1 = 0.f;
        if (MODE == 2) {
            const float* gm = mod + bidx * MODD + goff;
            gv0 = gm[col]; gv1 = gm[col + 1];
        }
        if (MODE >= 1 && bias) { bv0 = bias[col]; bv1 = bias[col + 1]; }
        #pragma unroll
        for (int mt = 0; mt < 4; mt++) {
            int r0 = rowBase + (warpM << 6) + (mt << 4) + g;
            #pragma unroll
            for (int half = 0; half < 2; half++) {
                int r = r0 + half * 8;
                float v0 = acc[mt][nt][half * 2];
                float v1 = acc[mt][nt][half * 2 + 1];
                size_t off = (size_t)r * N + col;
                if (MODE == 1) {
                    v0 = roundtf32(gelu_tanh(v0 + bv0));
                    v1 = roundtf32(gelu_tanh(v1 + bv1));
                } else if (MODE == 2) {
                    float2 rv = *(const float2*)(res + off);
                    v0 = rv.x + gv0 * (v0 + bv0);
                    v1 = rv.y + gv1 * (v1 + bv1);
                }
                *(float2*)(C + off) = make_float2(v0, v1);
            }
        }
    }
}

// ---------------- RMSNorm + RoPE for q,k; reshape v ----------------
__global__ void qkv_prep_kernel(const float* __restrict__ qkv,
                                const float* __restrict__ qw,
                                const float* __restrict__ kw,
                                const float* __restrict__ cosb,
                                const float* __restrict__ sinb,
                                float* __restrict__ qo,
                                float* __restrict__ ko,
                                float* __restrict__ vo)
{
    int gid  = blockIdx.x * blockDim.x + threadIdx.x;
    int lane = gid & 31;
    int widx = gid >> 5;
    int h = widx & 15;
    int s = (widx >> 4) & 2047;
    int b = widx >> 15;

    const float* base = qkv + (size_t)(b * SEQ + s) * (3 * DIM) + h * HDIM;
    float q1 = base[lane],            q2 = base[lane + 32];
    float k1 = base[DIM + lane],      k2 = base[DIM + lane + 32];
    float v1 = base[2 * DIM + lane],  v2 = base[2 * DIM + lane + 32];

    float ssq = q1 * q1 + q2 * q2;
    float ssk = k1 * k1 + k2 * k2;
    #pragma unroll
    for (int o = 16; o; o >>= 1) {
        ssq += __shfl_xor_sync(0xffffffffu, ssq, o);
        ssk += __shfl_xor_sync(0xffffffffu, ssk, o);
    }
    float rq = rsqrtf(ssq * (1.f / HDIM) + 1e-6f);
    float rk = rsqrtf(ssk * (1.f / HDIM) + 1e-6f);
    q1 *= rq * qw[lane];  q2 *= rq * qw[lane + 32];
    k1 *= rk * kw[lane];  k2 *= rk * kw[lane + 32];

    float c1 = cosb[s * HDIM + lane], c2 = cosb[s * HDIM + lane + 32];
    float s1 = sinb[s * HDIM + lane], s2 = sinb[s * HDIM + lane + 32];
    float oq1 = q1 * c1 - q2 * s1;
    float oq2 = q2 * c2 + q1 * s2;
    float ok1 = k1 * c1 - k2 * s1;
    float ok2 = k2 * c2 + k1 * s2;

    size_t off = ((size_t)(b * NHEAD + h) * SEQ + s) * HDIM;
    qo[off + lane] = oq1; qo[off + lane + 32] = oq2;
    ko[off + lane] = ok1; ko[off + lane + 32] = ok2;
    vo[off + lane] = v1;  vo[off + lane + 32] = v2;
}

// ---------------- Flash attention (tf32 MMA): 128 q-rows/block, 32-key tiles ----------------
__global__ __launch_bounds__(256, 2)
void attn_mma_kernel(const float* __restrict__ q, const float* __restrict__ k,
                     const float* __restrict__ v, float* __restrict__ out)
{
    __shared__ __align__(16) uint32_t Ks[32][68];
    __shared__ __align__(16) uint32_t Vs[32][72];
    __shared__ __align__(16) uint32_t Ps[128][36];

    const int tid  = threadIdx.x;
    const int warp = tid >> 5, lane = tid & 31;
    const int g = lane >> 2, tg = lane & 3;
    const int qt = blockIdx.x, h = blockIdx.y, b = blockIdx.z;
    const int bh = b * NHEAD + h;
    const float* kb = k + (size_t)bh * SEQ * HDIM;
    const float* vb = v + (size_t)bh * SEQ * HDIM;

    const float* qg = q + ((size_t)bh * SEQ + qt * 128 + warp * 16) * HDIM;
    uint32_t qa[8][4];
    #pragma unroll
    for (int kk = 0; kk < 8; kk++) {
        qa[kk][0] = f2tf32(0.125f * qg[(size_t)g       * HDIM + kk * 8 + tg]);
        qa[kk][1] = f2tf32(0.125f * qg[(size_t)(g + 8) * HDIM + kk * 8 + tg]);
        qa[kk][2] = f2tf32(0.125f * qg[(size_t)g       * HDIM + kk * 8 + tg + 4]);
        qa[kk][3] = f2tf32(0.125f * qg[(size_t)(g + 8) * HDIM + kk * 8 + tg + 4]);
    }

    float o[8][4] = {};
    float m0 = -1e30f, m1 = -1e30f, l0 = 0.f, l1 = 0.f;

    const int lr = tid >> 4;
    const int lc = (tid & 15) << 2;
    const int pr = warp * 16;

    for (int kt = 0; kt < SEQ / 32; kt++) {
        __syncthreads();
        #pragma unroll
        for (int i = 0; i < 2; i++) {
            int r = lr + i * 16;
            float4 kf = *(const float4*)(kb + (size_t)(kt * 32 + r) * HDIM + lc);
            uint4 kq; kq.x = f2tf32(kf.x); kq.y = f2tf32(kf.y);
            kq.z = f2tf32(kf.z); kq.w = f2tf32(kf.w);
            *(uint4*)&Ks[r][lc] = kq;
            float4 vf = *(const float4*)(vb + (size_t)(kt * 32 + r) * HDIM + lc);
            uint4 vq; vq.x = f2tf32(vf.x); vq.y = f2tf32(vf.y);
            vq.z = f2tf32(vf.z); vq.w = f2tf32(vf.w);
            *(uint4*)&Vs[r][lc] = vq;
        }
        __syncthreads();

        float s[4][4] = {};
        #pragma unroll
        for (int kk = 0; kk < 8; kk++) {
            #pragma unroll
            for (int nt = 0; nt < 4; nt++) {
                uint32_t b0 = Ks[nt * 8 + g][kk * 8 + tg];
                uint32_t b1 = Ks[nt * 8 + g][kk * 8 + tg + 4];
                mma_tf32(s[nt], qa[kk][0], qa[kk][1], qa[kk][2], qa[kk][3], b0, b1);
            }
        }

        float mx0 = -1e30f, mx1 = -1e30f;
        #pragma unroll
        for (int nt = 0; nt < 4; nt++) {
            mx0 = fmaxf(mx0, fmaxf(s[nt][0], s[nt][1]));
            mx1 = fmaxf(mx1, fmaxf(s[nt][2], s[nt][3]));
        }
        mx0 = fmaxf(mx0, __shfl_xor_sync(0xffffffffu, mx0, 1));
        mx0 = fmaxf(mx0, __shfl_xor_sync(0xffffffffu, mx0, 2));
        mx1 = fmaxf(mx1, __shfl_xor_sync(0xffffffffu, mx1, 1));
        mx1 = fmaxf(mx1, __shfl_xor_sync(0xffffffffu, mx1, 2));
        float nm0 = fmaxf(m0, mx0), nm1 = fmaxf(m1, mx1);
        float c0 = __expf(m0 - nm0), c1 = __expf(m1 - nm1);
        float sum0 = 0.f, sum1 = 0.f;
        #pragma unroll
        for (int nt = 0; nt < 4; nt++) {
            s[nt][0] = __expf(s[nt][0] - nm0);
            s[nt][1] = __expf(s[nt][1] - nm0);
            s[nt][2] = __expf(s[nt][2] - nm1);
            s[nt][3] = __expf(s[nt][3] - nm1);
            sum0 += s[nt][0] + s[nt][1];
            sum1 += s[nt][2] + s[nt][3];
        }
        sum0 += __shfl_xor_sync(0xffffffffu, sum0, 1);
        sum0 += __shfl_xor_sync(0xffffffffu, sum0, 2);
        sum1 += __shfl_xor_sync(0xffffffffu, sum1, 1);
        sum1 += __shfl_xor_sync(0xffffffffu, sum1, 2);
        l0 = l0 * c0 + sum0;
        l1 = l1 * c1 + sum1;
        m0 = nm0; m1 = nm1;

        #pragma unroll
        for (int nt = 0; nt < 8; nt++) {
            o[nt][0] *= c0; o[nt][1] *= c0;
            o[nt][2] *= c1; o[nt][3] *= c1;
        }

        #pragma unroll
        for (int nt = 0; nt < 4; nt++) {
            Ps[pr + g][nt * 8 + 2 * tg]         = f2tf32(s[nt][0]);
            Ps[pr + g][nt * 8 + 2 * tg + 1]     = f2tf32(s[nt][1]);
            Ps[pr + g + 8][nt * 8 + 2 * tg]     = f2tf32(s[nt][2]);
            Ps[pr + g + 8][nt * 8 + 2 * tg + 1] = f2tf32(s[nt][3]);
        }
        __syncwarp();

        #pragma unroll
        for (int kk = 0; kk < 4; kk++) {
            uint32_t a0 = Ps[pr + g][kk * 8 + tg];
            uint32_t a1 = Ps[pr + g + 8][kk * 8 + tg];
            uint32_t a2 = Ps[pr + g][kk * 8 + tg + 4];
            uint32_t a3 = Ps[pr + g + 8][kk * 8 + tg + 4];
            #pragma unroll
            for (int nt = 0; nt < 8; nt++) {
                uint32_t b0 = Vs[kk * 8 + tg][nt * 8 + g];
                uint32_t b1 = Vs[kk * 8 + tg + 4][nt * 8 + g];
                mma_tf32(o[nt], a0, a1, a2, a3, b0, b1);
            }
        }
    }

    // epilogue: normalize, tf32-round (feeds Wout GEMM), write [B,S,H*HD]
    float inv0 = 1.f / l0, inv1 = 1.f / l1;
    size_t rbase = (size_t)(b * SEQ + qt * 128 + warp * 16);
    #pragma unroll
    for (int nt = 0; nt < 8; nt++) {
        int col = h * HDIM + nt * 8 + 2 * tg;
        *(float2*)(out + (rbase + g) * DIM + col) =
            make_float2(roundtf32(o[nt][0] * inv0), roundtf32(o[nt][1] * inv0));
        *(float2*)(out + (rbase + g + 8) * DIM + col) =
            make_float2(roundtf32(o[nt][2] * inv1), roundtf32(o[nt][3] * inv1));
    }
}

// ---------------- launcher ----------------
extern "C" void kernel_launch(void* const* d_in, const int* in_sizes, int n_in,
                              void* d_out, int out_size)
{
    const float* x       = (const float*)d_in[0];
    const float* cosb    = (const float*)d_in[1];
    const float* sinb    = (const float*)d_in[2];
    const float* c       = (const float*)d_in[3];
    const float* norm1_w = (const float*)d_in[4];
    const float* Wqkv    = (const float*)d_in[5];
    const float* Wout    = (const float*)d_in[6];
    const float* q_norm_w= (const float*)d_in[7];
    const float* k_norm_w= (const float*)d_in[8];
    const float* norm2_w = (const float*)d_in[9];
    const float* W1      = (const float*)d_in[10];
    const float* b1      = (const float*)d_in[11];
    const float* W2      = (const float*)d_in[12];
    const float* b2      = (const float*)d_in[13];
    const float* ada_W   = (const float*)d_in[14];
    const float* ada_b   = (const float*)d_in[15];
    float* out = (float*)d_out;

    float *mod, *xn, *qkv, *qb, *kb, *vb, *attn, *x1, *hb;
    float *wqkv, *wout, *w1, *w2;
    cudaGetSymbolAddress((void**)&mod,  g_mod);
    cudaGetSymbolAddress((void**)&xn,   g_xn);
    cudaGetSymbolAddress((void**)&qkv,  g_qkv);
    cudaGetSymbolAddress((void**)&qb,   g_q);
    cudaGetSymbolAddress((void**)&kb,   g_k);
    cudaGetSymbolAddress((void**)&vb,   g_v);
    cudaGetSymbolAddress((void**)&attn, g_attn);
    cudaGetSymbolAddress((void**)&x1,   g_x1);
    cudaGetSymbolAddress((void**)&hb,   g_h);
    cudaGetSymbolAddress((void**)&wqkv, g_wqkv);
    cudaGetSymbolAddress((void**)&wout, g_wout);
    cudaGetSymbolAddress((void**)&w1,   g_w1);
    cudaGetSymbolAddress((void**)&w2,   g_w2);

    // 0. tf32-round weights into scratch
    round_copy_kernel<<<(DIM*3*DIM/4 + 255)/256, 256>>>(Wqkv, wqkv, DIM*3*DIM/4);
    round_copy_kernel<<<(DIM*DIM/4   + 255)/256, 256>>>(Wout, wout, DIM*DIM/4);
    round_copy_kernel<<<(DIM*DFF/4   + 255)/256, 256>>>(W1,   w1,   DIM*DFF/4);
    round_copy_kernel<<<(DFF*DIM/4   + 255)/256, 256>>>(W2,   w2,   DFF*DIM/4);

    // 1. adaLN modulation
    mod_kernel<<<dim3(MODD / 256, BATCH), 256>>>(c, ada_W, ada_b, mod);
    // 2. LN1 + modulate (tf32-rounded out)
    ln_mod_kernel<<<NTOK, 256>>>(x, norm1_w, mod, 0, 1024, xn);
    // 3. QKV GEMM
    mma_gemm<0><<<dim3(3 * DIM / BN, NTOK / BM), 256>>>(
        xn, wqkv, qkv, NTOK, 3 * DIM, DIM, nullptr, nullptr, nullptr, 0);
    // 4. RMSNorm + RoPE
    qkv_prep_kernel<<<(BATCH * SEQ * NHEAD) / 8, 256>>>(
        qkv, q_norm_w, k_norm_w, cosb, sinb, qb, kb, vb);
    // 5. attention (tf32 MMA flash, rounded out)
    attn_mma_kernel<<<dim3(SEQ / 128, NHEAD, BATCH), 256>>>(qb, kb, vb, attn);
    // 6. out proj + gate + residual  -> x1
    mma_gemm<2><<<dim3(DIM / BN, NTOK / BM), 256>>>(
        attn, wout, x1, NTOK, DIM, DIM, nullptr, x, mod, 2048);
    // 7. LN2 + modulate (tf32-rounded out)
    ln_mod_kernel<<<NTOK, 256>>>(x1, norm2_w, mod, 3072, 4096, xn);
    // 8. MLP up + GELU (rounded out)
    mma_gemm<1><<<dim3(DFF / BN, NTOK / BM), 256>>>(
        xn, w1, hb, NTOK, DFF, DIM, b1, nullptr, nullptr, 0);
    // 9. MLP down + gate + residual -> out
    mma_gemm<2><<<dim3(DIM / BN, NTOK / BM), 256>>>(
        hb, w2, out, NTOK, DIM, DFF, b2, x1, mod, 5120);
}

// round 16
// speedup vs baseline: 6.0601x; 1.9383x over previous
#include <cuda_runtime.h>
#include <cuda_fp16.h>
#include <cstdint>

// Problem constants
#define BATCH 4
#define SEQ   2048
#define DIM   1024
#define NHEAD 16
#define HDIM  64
#define DFF   4096
#define NTOK  (BATCH*SEQ)          // 8192
#define MODD  6144                 // 6*DIM

// ---------------- scratch (__device__ globals; allocation-free) ----------------
__device__ float  g_mod [BATCH*MODD];
__device__ __half g_xn  [NTOK*DIM];
__device__ __half g_qkv [NTOK*3*DIM];
__device__ __half g_q   [BATCH*NHEAD*SEQ*HDIM];
__device__ __half g_k   [BATCH*NHEAD*SEQ*HDIM];
__device__ __half g_v   [BATCH*NHEAD*SEQ*HDIM];
__device__ __half g_attn[NTOK*DIM];
__device__ float  g_x1  [NTOK*DIM];
__device__ __half g_h   [NTOK*DFF];
// fp16, TRANSPOSED ([n][k] K-major) weight copies
__device__ __half g_wqkv[3*DIM*DIM];
__device__ __half g_wout[DIM*DIM];
__device__ __half g_w1  [DFF*DIM];
__device__ __half g_w2  [DIM*DFF];

// ---------------- helpers ----------------
__device__ __forceinline__ void mma_f16(float* c,
                                        uint32_t a0, uint32_t a1, uint32_t a2, uint32_t a3,
                                        uint32_t b0, uint32_t b1)
{
    asm volatile("mma.sync.aligned.m16n8k16.row.col.f32.f16.f16.f32 "
                 "{%0,%1,%2,%3}, {%4,%5,%6,%7}, {%8,%9}, {%0,%1,%2,%3};"
                 : "+f"(c[0]), "+f"(c[1]), "+f"(c[2]), "+f"(c[3])
                 : "r"(a0), "r"(a1), "r"(a2), "r"(a3), "r"(b0), "r"(b1));
}

__device__ __forceinline__ uint32_t smem_u32(const void* p)
{
    return (uint32_t)__cvta_generic_to_shared(p);
}

__device__ __forceinline__ void cpasync16(uint32_t dst, const void* src)
{
    asm volatile("cp.async.cg.shared.global [%0], [%1], 16;" :: "r"(dst), "l"(src));
}

__device__ __forceinline__ void ldsm_x4(uint32_t* r, uint32_t addr)
{
    asm volatile("ldmatrix.sync.aligned.m8n8.x4.shared.b16 {%0,%1,%2,%3}, [%4];"
                 : "=r"(r[0]), "=r"(r[1]), "=r"(r[2]), "=r"(r[3]) : "r"(addr));
}
__device__ __forceinline__ void ldsm_x2(uint32_t* r, uint32_t addr)
{
    asm volatile("ldmatrix.sync.aligned.m8n8.x2.shared.b16 {%0,%1}, [%2];"
                 : "=r"(r[0]), "=r"(r[1]) : "r"(addr));
}
__device__ __forceinline__ void ldsm_x2t(uint32_t* r, uint32_t addr)
{
    asm volatile("ldmatrix.sync.aligned.m8n8.x2.trans.shared.b16 {%0,%1}, [%2];"
                 : "=r"(r[0]), "=r"(r[1]) : "r"(addr));
}

__device__ __forceinline__ float gelu_tanh(float x)
{
    float x3 = x * x * x;
    return 0.5f * x * (1.f + tanhf(0.7978845608028654f * (x + 0.044715f * x3)));
}

// ---------------- weight fp16 + transpose: dst[n][k] = h(src[k][n]) ----------------
__global__ void round_transpose_kernel(const float* __restrict__ src,
                                       __half* __restrict__ dst, int K, int N)
{
    __shared__ float tile[32][33];
    int n0 = blockIdx.x * 32, k0 = blockIdx.y * 32;
    int tx = threadIdx.x, ty = threadIdx.y;
    #pragma unroll
    for (int i = 0; i < 4; i++)
        tile[ty + i * 8][tx] = src[(size_t)(k0 + ty + i * 8) * N + n0 + tx];
    __syncthreads();
    #pragma unroll
    for (int i = 0; i < 4; i++)
        dst[(size_t)(n0 + ty + i * 8) * K + k0 + tx] = __float2half(tile[tx][ty + i * 8]);
}

// ---------------- adaLN modulation: mod = c @ ada_W + ada_b ----------------
__global__ void mod_kernel(const float* __restrict__ c,
                           const float* __restrict__ adaW,
                           const float* __restrict__ adab,
                           float* __restrict__ mod)
{
    int j = blockIdx.x * 256 + threadIdx.x;
    int b = blockIdx.y;
    const float* crow = c + b * 1024;
    float acc = adab[j];
    #pragma unroll 4
    for (int k = 0; k < 1024; k++)
        acc = fmaf(__ldg(crow + k), __ldg(adaW + (size_t)k * MODD + j), acc);
    mod[b * MODD + j] = acc;
}

// ---------------- LayerNorm + adaLN modulate (fp16 out) ----------------
__global__ void ln_mod_kernel(const float* __restrict__ x,
                              const float* __restrict__ w,
                              const float* __restrict__ mod,
                              int sh_off, int sc_off,
                              __half* __restrict__ out)
{
    __shared__ float red[16];
    __shared__ float stats[2];
    int t = blockIdx.x;
    int b = t >> 11;
    const float4* xr = (const float4*)(x + (size_t)t * DIM);
    float4 xv = xr[threadIdx.x];

    float s  = xv.x + xv.y + xv.z + xv.w;
    float sq = xv.x*xv.x + xv.y*xv.y + xv.z*xv.z + xv.w*xv.w;
    #pragma unroll
    for (int o = 16; o; o >>= 1) {
        s  += __shfl_down_sync(0xffffffffu, s,  o);
        sq += __shfl_down_sync(0xffffffffu, sq, o);
    }
    int wid = threadIdx.x >> 5, lane = threadIdx.x & 31;
    if (lane == 0) { red[wid] = s; red[wid + 8] = sq; }
    __syncthreads();
    if (threadIdx.x == 0) {
        float ts = 0.f, tq = 0.f;
        #pragma unroll
        for (int i = 0; i < 8; i++) { ts += red[i]; tq += red[i + 8]; }
        float mu  = ts * (1.f / DIM);
        float var = tq * (1.f / DIM) - mu * mu;
        stats[0] = mu;
        stats[1] = rsqrtf(var + 1e-5f);
    }
    __syncthreads();
    float mu = stats[0], rstd = stats[1];

    const float* modb = mod + b * MODD;
    float4 wv = ((const float4*)w)[threadIdx.x];
    float4 sc = ((const float4*)(modb + sc_off))[threadIdx.x];
    float4 sh = ((const float4*)(modb + sh_off))[threadIdx.x];
    __half2 h0 = __floats2half2_rn((xv.x - mu) * rstd * wv.x * (1.f + sc.x) + sh.x,
                                   (xv.y - mu) * rstd * wv.y * (1.f + sc.y) + sh.y);
    __half2 h1 = __floats2half2_rn((xv.z - mu) * rstd * wv.z * (1.f + sc.z) + sh.z,
                                   (xv.w - mu) * rstd * wv.w * (1.f + sc.w) + sh.w);
    uint2 pk = make_uint2(*(uint32_t*)&h0, *(uint32_t*)&h1);
    ((uint2*)(out + (size_t)t * DIM))[threadIdx.x] = pk;
}

// ---------------- fp16 tensor-core GEMM, 128x128 block, BK=64, cp.async + ldmatrix ----------------
// A: [M][K] half.  BT: [N][K] half (= W^T, K-major).  C[m][n] = sum_k A[m][k]*BT[n][k]
// MODE 0: C(half) = A@W ; MODE 1: C(half) = gelu(A@W + bias) ; MODE 2: C(float) = res + g*(A@W + bias)
#define BM 128
#define BN 128
#define BK 64
#define HSTR 72   // smem row stride in halves (144 B): +4 banks/row -> conflict-free ldmatrix

template<int MODE>
__global__ __launch_bounds__(256, 2)
void mma_gemm(const __half* __restrict__ A, const __half* __restrict__ BT,
              void* __restrict__ Cv, int M, int N, int K,
              const float* __restrict__ bias,
              const float* __restrict__ res,
              const float* __restrict__ mod, int goff)
{
    extern __shared__ __align__(16) char dsm[];
    __half* As = (__half*)dsm;                         // [2][128*HSTR]
    __half* Bs = (__half*)(dsm + 2 * BM * HSTR * 2);   // [2][128*HSTR]

    const int tid  = threadIdx.x;
    const int lane = tid & 31, warp = tid >> 5;
    const int g = lane >> 2, tg = lane & 3;
    const int warpM = warp & 1, warpN = warp >> 1;     // 2 x 4 warps; warp tile 64x32
    const int rowBase = blockIdx.y << 7, colBase = blockIdx.x << 7;

    const __half* Ag = A  + (size_t)rowBase * K;
    const __half* Bg = BT + (size_t)colBase * K;

    // loader mapping: idx = tid + i*256 -> row = idx>>3 (0..127), chunk c = idx&7 (16B)
    auto issue = [&](int kt, int buf) {
        const uint32_t ab = smem_u32(As) + buf * (BM * HSTR * 2);
        const uint32_t bb = smem_u32(Bs) + buf * (BM * HSTR * 2);
        #pragma unroll
        for (int i = 0; i < 4; i++) {
            int idx = tid + i * 256;
            int r = idx >> 3, c = idx & 7;
            cpasync16(ab + r * (HSTR * 2) + c * 16, Ag + (size_t)r * K + kt * BK + c * 8);
            cpasync16(bb + r * (HSTR * 2) + c * 16, Bg + (size_t)r * K + kt * BK + c * 8);
        }
        asm volatile("cp.async.commit_group;" ::: "memory");
    };

    // ldmatrix lane offsets
    const int aRow = (lane & 7) + (lane & 8);          // rows of A 16x16 tile
    const uint32_t aOff = aRow * (HSTR * 2) + (lane & 16);  // +16B for col-8 matrices
    const int bRow = lane & 7;
    const uint32_t bOff = bRow * (HSTR * 2) + ((lane & 8) << 1);  // matrix1 at +8 halves

    issue(0, 0);

    float acc[4][4][4] = {};
    const int ntiles = K / BK;

    for (int kt = 0; kt < ntiles; kt++) {
        const int buf = kt & 1;
        if (kt + 1 < ntiles) {
            issue(kt + 1, buf ^ 1);
            asm volatile("cp.async.wait_group 1;" ::: "memory");
        } else {
            asm volatile("cp.async.wait_group 0;" ::: "memory");
        }
        __syncthreads();

        const uint32_t ab = smem_u32(As) + buf * (BM * HSTR * 2);
        const uint32_t bb = smem_u32(Bs) + buf * (BM * HSTR * 2);

        #pragma unroll
        for (int kc = 0; kc < 4; kc++) {
            uint32_t af[4][4], bf[4][2];
            #pragma unroll
            for (int mt = 0; mt < 4; mt++) {
                int m0 = (warpM << 6) + (mt << 4);
                ldsm_x4(af[mt], ab + m0 * (HSTR * 2) + kc * 32 + aOff);
            }
            #pragma unroll
            for (int nt = 0; nt < 4; nt++) {
                int n0 = (warpN << 5) + (nt << 3);
                ldsm_x2(bf[nt], bb + n0 * (HSTR * 2) + kc * 32 + bOff);
            }
            #pragma unroll
            for (int mt = 0; mt < 4; mt++)
                #pragma unroll
                for (int nt = 0; nt < 4; nt++)
                    mma_f16(acc[mt][nt],
                            af[mt][0], af[mt][1], af[mt][2], af[mt][3],
                            bf[nt][0], bf[nt][1]);
        }
        __syncthreads();
    }

    // epilogue
    const int bidx = rowBase >> 11;
    #pragma unroll
    for (int nt = 0; nt < 4; nt++) {
        int col = colBase + (warpN << 5) + (nt << 3) + (tg << 1);
        float gv0 = 0.f, gv1 = 0.f, bv0 = 0.f, bv1 = 0.f;
        if (MODE == 2) {
            const float* gm = mod + bidx * MODD + goff;
            gv0 = gm[col]; gv1 = gm[col + 1];
        }
        if (MODE >= 1 && bias) { bv0 = bias[col]; bv1 = bias[col + 1]; }
        #pragma unroll
        for (int mt = 0; mt < 4; mt++) {
            int r0 = rowBase + (warpM << 6) + (mt << 4) + g;
            #pragma unroll
            for (int half = 0; half < 2; half++) {
                int r = r0 + half * 8;
                float v0 = acc[mt][nt][half * 2];
                float v1 = acc[mt][nt][half * 2 + 1];
                size_t off = (size_t)r * N + col;
                if (MODE == 2) {
                    float* C = (float*)Cv;
                    float2 rv = *(const float2*)(res + off);
                    v0 = rv.x + gv0 * (v0 + bv0);
                    v1 = rv.y + gv1 * (v1 + bv1);
                    *(float2*)(C + off) = make_float2(v0, v1);
                } else {
                    if (MODE == 1) {
                        v0 = gelu_tanh(v0 + bv0);
                        v1 = gelu_tanh(v1 + bv1);
                    }
                    __half* C = (__half*)Cv;
                    *(__half2*)(C + off) = __floats2half2_rn(v0, v1);
                }
            }
        }
    }
}

// ---------------- RMSNorm + RoPE for q,k; reshape v (half in/out) ----------------
// q is pre-scaled by 1/sqrt(HD) = 0.125
__global__ void qkv_prep_kernel(const __half* __restrict__ qkv,
                                const float* __restrict__ qw,
                                const float* __restrict__ kw,
                                const float* __restrict__ cosb,
                                const float* __restrict__ sinb,
                                __half* __restrict__ qo,
                                __half* __restrict__ ko,
                                __half* __restrict__ vo)
{
    int gid  = blockIdx.x * blockDim.x + threadIdx.x;
    int lane = gid & 31;
    int widx = gid >> 5;
    int h = widx & 15;
    int s = (widx >> 4) & 2047;
    int b = widx >> 15;

    const __half* base = qkv + (size_t)(b * SEQ + s) * (3 * DIM) + h * HDIM;
    float q1 = __half2float(base[lane]),           q2 = __half2float(base[lane + 32]);
    float k1 = __half2float(base[DIM + lane]),     k2 = __half2float(base[DIM + lane + 32]);
    float v1 = __half2float(base[2*DIM + lane]),   v2 = __half2float(base[2*DIM + lane + 32]);

    float ssq = q1 * q1 + q2 * q2;
    float ssk = k1 * k1 + k2 * k2;
    #pragma unroll
    for (int o = 16; o; o >>= 1) {
        ssq += __shfl_xor_sync(0xffffffffu, ssq, o);
        ssk += __shfl_xor_sync(0xffffffffu, ssk, o);
    }
    float rq = rsqrtf(ssq * (1.f / HDIM) + 1e-6f);
    float rk = rsqrtf(ssk * (1.f / HDIM) + 1e-6f);
    q1 *= rq * qw[lane];  q2 *= rq * qw[lane + 32];
    k1 *= rk * kw[lane];  k2 *= rk * kw[lane + 32];

    float c1 = cosb[s * HDIM + lane], c2 = cosb[s * HDIM + lane + 32];
    float s1 = sinb[s * HDIM + lane], s2 = sinb[s * HDIM + lane + 32];
    float oq1 = (q1 * c1 - q2 * s1) * 0.125f;
    float oq2 = (q2 * c2 + q1 * s2) * 0.125f;
    float ok1 = k1 * c1 - k2 * s1;
    float ok2 = k2 * c2 + k1 * s2;

    size_t off = ((size_t)(b * NHEAD + h) * SEQ + s) * HDIM;
    qo[off + lane] = __float2half(oq1); qo[off + lane + 32] = __float2half(oq2);
    ko[off + lane] = __float2half(ok1); ko[off + lane + 32] = __float2half(ok2);
    vo[off + lane] = __float2half(v1);  vo[off + lane + 32] = __float2half(v2);
}

// ---------------- Flash attention (fp16 MMA): 128 q-rows/block, 32-key tiles ----------------
// 8 warps x 16 q-rows. P stays in registers (S C-frag == PV A-frag layout).
__global__ __launch_bounds__(256, 2)
void attn_mma_kernel(const __half* __restrict__ q, const __half* __restrict__ k,
                     const __half* __restrict__ v, __half* __restrict__ out)
{
    __shared__ __align__(16) __half Ks[32][HSTR];
    __shared__ __align__(16) __half Vs[32][HSTR];

    const int tid  = threadIdx.x;
    const int warp = tid >> 5, lane = tid & 31;
    const int g = lane >> 2, tg = lane & 3;
    const int qt = blockIdx.x, h = blockIdx.y, b = blockIdx.z;
    const int bh = b * NHEAD + h;
    const __half* kb = k + (size_t)bh * SEQ * HDIM;
    const __half* vb = v + (size_t)bh * SEQ * HDIM;

    // Q fragments from global (q already scaled by 1/8)
    const __half* qg = q + ((size_t)bh * SEQ + qt * 128 + warp * 16) * HDIM;
    uint32_t qa[4][4];
    #pragma unroll
    for (int kc = 0; kc < 4; kc++) {
        qa[kc][0] = *(const uint32_t*)(qg + (size_t)g       * HDIM + kc * 16 + 2 * tg);
        qa[kc][1] = *(const uint32_t*)(qg + (size_t)(g + 8) * HDIM + kc * 16 + 2 * tg);
        qa[kc][2] = *(const uint32_t*)(qg + (size_t)g       * HDIM + kc * 16 + 8 + 2 * tg);
        qa[kc][3] = *(const uint32_t*)(qg + (size_t)(g + 8) * HDIM + kc * 16 + 8 + 2 * tg);
    }

    float o[8][4] = {};
    float m0 = -1e30f, m1 = -1e30f, l0 = 0.f, l1 = 0.f;

    const int lr = tid >> 3;          // 0..31 load row
    const int lc = tid & 7;           // 16B chunk

    // ldmatrix lane offsets
    const uint32_t kOff = (lane & 7) * (HSTR * 2) + ((lane & 8) << 1);  // K b-frags
    const uint32_t vOff = (lane & 15) * (HSTR * 2);                     // V b-frags (trans)

    for (int kt = 0; kt < SEQ / 32; kt++) {
        __syncthreads();
        *(uint4*)&Ks[lr][lc * 8] = *(const uint4*)(kb + (size_t)(kt * 32 + lr) * HDIM + lc * 8);
        *(uint4*)&Vs[lr][lc * 8] = *(const uint4*)(vb + (size_t)(kt * 32 + lr) * HDIM + lc * 8);
        __syncthreads();

        // S = Q K^T : 16 rows x 32 keys per warp
        float s[4][4] = {};
        #pragma unroll
        for (int kc = 0; kc < 4; kc++) {
            #pragma unroll
            for (int nt = 0; nt < 4; nt++) {
                uint32_t bf[2];
                ldsm_x2(bf, smem_u32(&Ks[nt * 8][0]) + kc * 32 + kOff);
                mma_f16(s[nt], qa[kc][0], qa[kc][1], qa[kc][2], qa[kc][3], bf[0], bf[1]);
            }
        }

        // online softmax (rows g and g+8)
        float mx0 = -1e30f, mx1 = -1e30f;
        #pragma unroll
        for (int nt = 0; nt < 4; nt++) {
            mx0 = fmaxf(mx0, fmaxf(s[nt][0], s[nt][1]));
            mx1 = fmaxf(mx1, fmaxf(s[nt][2], s[nt][3]));
        }
        mx0 = fmaxf(mx0, __shfl_xor_sync(0xffffffffu, mx0, 1));
        mx0 = fmaxf(mx0, __shfl_xor_sync(0xffffffffu, mx0, 2));
        mx1 = fmaxf(mx1, __shfl_xor_sync(0xffffffffu, mx1, 1));
        mx1 = fmaxf(mx1, __shfl_xor_sync(0xffffffffu, mx1, 2));
        float nm0 = fmaxf(m0, mx0), nm1 = fmaxf(m1, mx1);
        float c0 = __expf(m0 - nm0), c1 = __expf(m1 - nm1);
        float sum0 = 0.f, sum1 = 0.f;
        #pragma unroll
        for (int nt = 0; nt < 4; nt++) {
            s[nt][0] = __expf(s[nt][0] - nm0);
            s[nt][1] = __expf(s[nt][1] - nm0);
            s[nt][2] = __expf(s[nt][2] - nm1);
            s[nt][3] = __expf(s[nt][3] - nm1);
            sum0 += s[nt][0] + s[nt][1];
            sum1 += s[nt][2] + s[nt][3];
        }
        sum0 += __shfl_xor_sync(0xffffffffu, sum0, 1);
        sum0 += __shfl_xor_sync(0xffffffffu, sum0, 2);
        sum1 += __shfl_xor_sync(0xffffffffu, sum1, 1);
        sum1 += __shfl_xor_sync(0xffffffffu, sum1, 2);
        l0 = l0 * c0 + sum0;
        l1 = l1 * c1 + sum1;
        m0 = nm0; m1 = nm1;

        #pragma unroll
        for (int nt = 0; nt < 8; nt++) {
            o[nt][0] *= c0; o[nt][1] *= c0;
            o[nt][2] *= c1; o[nt][3] *= c1;
        }

        // P A-frags directly from S C-frags (no smem round-trip)
        uint32_t pa[2][4];
        #pragma unroll
        for (int kc = 0; kc < 2; kc++) {
            __half2 h0 = __floats2half2_rn(s[2*kc][0],   s[2*kc][1]);
            __half2 h1 = __floats2half2_rn(s[2*kc][2],   s[2*kc][3]);
            __half2 h2 = __floats2half2_rn(s[2*kc+1][0], s[2*kc+1][1]);
            __half2 h3 = __floats2half2_rn(s[2*kc+1][2], s[2*kc+1][3]);
            pa[kc][0] = *(uint32_t*)&h0; pa[kc][1] = *(uint32_t*)&h1;
            pa[kc][2] = *(uint32_t*)&h2; pa[kc][3] = *(uint32_t*)&h3;
        }

        // O += P V  (V b-frags via ldmatrix.trans on [key][d])
        #pragma unroll
        for (int kc = 0; kc < 2; kc++) {
            #pragma unroll
            for (int dn = 0; dn < 8; dn++) {
                uint32_t bf[2];
                ldsm_x2t(bf, smem_u32(&Vs[kc * 16][0]) + dn * 16 + vOff);
                mma_f16(o[dn], pa[kc][0], pa[kc][1], pa[kc][2], pa[kc][3], bf[0], bf[1]);
            }
        }
    }

    // epilogue: normalize, write half [B,S,H*HD]
    float inv0 = 1.f / l0, inv1 = 1.f / l1;
    size_t rbase = (size_t)(b * SEQ + qt * 128 + warp * 16);
    #pragma unroll
    for (int dn = 0; dn < 8; dn++) {
        int col = h * HDIM + dn * 8 + 2 * tg;
        *(__half2*)(out + (rbase + g) * DIM + col) =
            __floats2half2_rn(o[dn][0] * inv0, o[dn][1] * inv0);
        *(__half2*)(out + (rbase + g + 8) * DIM + col) =
            __floats2half2_rn(o[dn][2] * inv1, o[dn][3] * inv1);
    }
}

// ---------------- launcher ----------------
extern "C" void kernel_launch(void* const* d_in, const int* in_sizes, int n_in,
                              void* d_out, int out_size)
{
    const float* x       = (const float*)d_in[0];
    const float* cosb    = (const float*)d_in[1];
    const float* sinb    = (const float*)d_in[2];
    const float* c       = (const float*)d_in[3];
    const float* norm1_w = (const float*)d_in[4];
    const float* Wqkv    = (const float*)d_in[5];
    const float* Wout    = (const float*)d_in[6];
    const float* q_norm_w= (const float*)d_in[7];
    const float* k_norm_w= (const float*)d_in[8];
    const float* norm2_w = (const float*)d_in[9];
    const float* W1      = (const float*)d_in[10];
    const float* b1      = (const float*)d_in[11];
    const float* W2      = (const float*)d_in[12];
    const float* b2      = (const float*)d_in[13];
    const float* ada_W   = (const float*)d_in[14];
    const float* ada_b   = (const float*)d_in[15];
    float* out = (float*)d_out;

    float *mod, *x1;
    __half *xn, *qkv, *qb, *kb, *vb, *attn, *hb, *wqkv, *wout, *w1, *w2;
    cudaGetSymbolAddress((void**)&mod,  g_mod);
    cudaGetSymbolAddress((void**)&xn,   g_xn);
    cudaGetSymbolAddress((void**)&qkv,  g_qkv);
    cudaGetSymbolAddress((void**)&qb,   g_q);
    cudaGetSymbolAddress((void**)&kb,   g_k);
    cudaGetSymbolAddress((void**)&vb,   g_v);
    cudaGetSymbolAddress((void**)&attn, g_attn);
    cudaGetSymbolAddress((void**)&x1,   g_x1);
    cudaGetSymbolAddress((void**)&hb,   g_h);
    cudaGetSymbolAddress((void**)&wqkv, g_wqkv);
    cudaGetSymbolAddress((void**)&wout, g_wout);
    cudaGetSymbolAddress((void**)&w1,   g_w1);
    cudaGetSymbolAddress((void**)&w2,   g_w2);

    // dynamic smem for the GEMM: 2 bufs x (A+B) x 128*72 halves = 73728 B
    const int SMEM_DYN = 4 * BM * HSTR * 2;
    cudaFuncSetAttribute(mma_gemm<0>, cudaFuncAttributeMaxDynamicSharedMemorySize, SMEM_DYN);
    cudaFuncSetAttribute(mma_gemm<1>, cudaFuncAttributeMaxDynamicSharedMemorySize, SMEM_DYN);
    cudaFuncSetAttribute(mma_gemm<2>, cudaFuncAttributeMaxDynamicSharedMemorySize, SMEM_DYN);

    dim3 tb(32, 8);
    // 0. fp16 + transpose weights into scratch ([n][k] K-major)
    round_transpose_kernel<<<dim3(3 * DIM / 32, DIM / 32), tb>>>(Wqkv, wqkv, DIM, 3 * DIM);
    round_transpose_kernel<<<dim3(DIM / 32, DIM / 32), tb>>>(Wout, wout, DIM, DIM);
    round_transpose_kernel<<<dim3(DFF / 32, DIM / 32), tb>>>(W1, w1, DIM, DFF);
    round_transpose_kernel<<<dim3(DIM / 32, DFF / 32), tb>>>(W2, w2, DFF, DIM);

    // 1. adaLN modulation
    mod_kernel<<<dim3(MODD / 256, BATCH), 256>>>(c, ada_W, ada_b, mod);
    // 2. LN1 + modulate (half out)
    ln_mod_kernel<<<NTOK, 256>>>(x, norm1_w, mod, 0, 1024, xn);
    // 3. QKV GEMM (fp16 MMA) -> half
    mma_gemm<0><<<dim3(3 * DIM / BN, NTOK / BM), 256, SMEM_DYN>>>(
        xn, wqkv, qkv, NTOK, 3 * DIM, DIM, nullptr, nullptr, nullptr, 0);
    // 4. RMSNorm + RoPE (q pre-scaled)
    qkv_prep_kernel<<<(BATCH * SEQ * NHEAD) / 8, 256>>>(
        qkv, q_norm_w, k_norm_w, cosb, sinb, qb, kb, vb);
    // 5. attention (fp16 MMA flash) -> half
    attn_mma_kernel<<<dim3(SEQ / 128, NHEAD, BATCH), 256>>>(qb, kb, vb, attn);
    // 6. out proj + gate + residual -> x1 (float)
    mma_gemm<2><<<dim3(DIM / BN, NTOK / BM), 256, SMEM_DYN>>>(
        attn, wout, x1, NTOK, DIM, DIM, nullptr, x, mod, 2048);
    // 7. LN2 + modulate (half out)
    ln_mod_kernel<<<NTOK, 256>>>(x1, norm2_w, mod, 3072, 4096, xn);
    // 8. MLP up + GELU -> half
    mma_gemm<1><<<dim3(DFF / BN, NTOK / BM), 256, SMEM_DYN>>>(
        xn, w1, hb, NTOK, DFF, DIM, b1, nullptr, nullptr, 0);
    // 9. MLP down + gate + residual -> out (float)
    mma_gemm<2><<<dim3(DIM / BN, NTOK / BM), 256, SMEM_DYN>>>(
        hb, w2, out, NTOK, DIM, DFF, b2, x1, mod, 5120);
}